// round 1
// baseline (speedup 1.0000x reference)
#include <cuda_runtime.h>
#include <math.h>

#define BATCH 8
#define SEQL 2048
#define ROWS (BATCH*SEQL)     // 16384
#define DMODEL 256
#define DINNER 512
#define DSTATE 64
#define CONVDIM 640
#define DINPROJ 1153
#define QC 128                // chunk length
#define NCH (SEQL/QC)         // 16 chunks

// ---------------- scratch (device globals; no allocation allowed) ----------
__device__ float g_res[ROWS*DMODEL];
__device__ float g_hid[ROWS*DMODEL];
__device__ float g_hn [ROWS*DMODEL];
__device__ float g_zx [ROWS*DINPROJ];
__device__ float g_xbc[ROWS*CONVDIM];
__device__ float g_y  [ROWS*DINNER];
__device__ float g_dt [ROWS];
__device__ float g_cum[ROWS];
__device__ float g_S[BATCH*NCH*DSTATE*DINNER];
__device__ float g_H[BATCH*NCH*DSTATE*DINNER];

// ---------------- embed gather ----------------
__global__ __launch_bounds__(256) void k_embed(const int* __restrict__ ids,
                                               const float* __restrict__ embed) {
    int row = blockIdx.x, t = threadIdx.x;
    g_res[row*DMODEL + t] = embed[ids[row]*DMODEL + t];
}

// ---------------- residual add + rmsnorm -> g_hn ----------------
__global__ __launch_bounds__(256) void k_resnorm(const float* __restrict__ w, int add) {
    int row = blockIdx.x, t = threadIdx.x;
    float v = g_res[row*DMODEL + t];
    if (add) { v += g_hid[row*DMODEL + t]; g_res[row*DMODEL + t] = v; }
    __shared__ float sred[256];
    sred[t] = v*v; __syncthreads();
    #pragma unroll
    for (int s = 128; s > 0; s >>= 1) {
        if (t < s) sred[t] += sred[t+s];
        __syncthreads();
    }
    float rs = rsqrtf(sred[0]*(1.f/DMODEL) + 1e-5f);
    g_hn[row*DMODEL + t] = v * rs * w[t];
}

// ---------------- SGEMM: C[M,N] = A[M,K] * B[N,K]^T (both row-major, K-major)
// which==0: A=g_hn, C=g_zx (in_proj).  which==1: A=g_y, C=g_hid (out_proj).
__global__ __launch_bounds__(256) void sgemm_nt(int which, const float* __restrict__ Bm,
                                                int M, int N, int K) {
    const float* A; float* C;
    if (which == 0) { A = g_hn; C = g_zx; } else { A = g_y; C = g_hid; }
    __shared__ __align__(16) float As[16][128];
    __shared__ __align__(16) float Bs[16][64];
    int bm = blockIdx.y*128, bn = blockIdx.x*64;
    int tid = threadIdx.x;
    int mt = tid >> 4, nt = tid & 15;            // micro tile: rows mt*8..+8, cols nt*4..+4
    int arow = tid >> 1, acol = (tid & 1)*8;     // A loader
    int brow = tid >> 2, bcol = (tid & 3)*4;     // B loader
    float acc[8][4];
    #pragma unroll
    for (int i = 0; i < 8; i++)
        #pragma unroll
        for (int j = 0; j < 4; j++) acc[i][j] = 0.f;

    for (int k0 = 0; k0 < K; k0 += 16) {
        #pragma unroll
        for (int j = 0; j < 8; j++)
            As[acol+j][arow] = A[(bm+arow)*K + k0 + acol + j];
        int nb = bn + brow; bool nv = nb < N;
        #pragma unroll
        for (int j = 0; j < 4; j++)
            Bs[bcol+j][brow] = nv ? Bm[nb*K + k0 + bcol + j] : 0.f;
        __syncthreads();
        #pragma unroll
        for (int kk = 0; kk < 16; kk++) {
            float4 a0 = *(const float4*)&As[kk][mt*8];
            float4 a1 = *(const float4*)&As[kk][mt*8+4];
            float4 bv = *(const float4*)&Bs[kk][nt*4];
            float a[8] = {a0.x,a0.y,a0.z,a0.w,a1.x,a1.y,a1.z,a1.w};
            float b[4] = {bv.x,bv.y,bv.z,bv.w};
            #pragma unroll
            for (int i = 0; i < 8; i++)
                #pragma unroll
                for (int j = 0; j < 4; j++) acc[i][j] += a[i]*b[j];
        }
        __syncthreads();
    }
    #pragma unroll
    for (int i = 0; i < 8; i++) {
        int m = bm + mt*8 + i;
        #pragma unroll
        for (int j = 0; j < 4; j++) {
            int n = bn + nt*4 + j;
            if (n < N) C[m*N + n] = acc[i][j];
        }
    }
}

// ---------------- depthwise causal conv (window 4) + silu ----------------
__global__ __launch_bounds__(256) void k_conv(const float* __restrict__ cw,
                                              const float* __restrict__ cb) {
    int idx = blockIdx.x*256 + threadIdx.x;
    if (idx >= ROWS*CONVDIM) return;
    int c = idx % CONVDIM, row = idx / CONVDIM;
    int t = row & (SEQL-1);
    float w0 = cw[c*4+0], w1 = cw[c*4+1], w2 = cw[c*4+2], w3 = cw[c*4+3];
    float acc = cb[c];
    const float* base = g_zx + (size_t)row*DINPROJ + DINNER + c;
    if (t >= 3) acc += base[-3*DINPROJ]*w0;
    if (t >= 2) acc += base[-2*DINPROJ]*w1;
    if (t >= 1) acc += base[-1*DINPROJ]*w2;
    acc += base[0]*w3;
    g_xbc[idx] = acc / (1.f + expf(-acc));   // silu
}

// ---------------- dt = softplus(raw + dtb); per-chunk inclusive cumsum of dt*A ----
__global__ __launch_bounds__(128) void k_dtcum(const float* __restrict__ dtb,
                                               const float* __restrict__ alog) {
    int bc = blockIdx.x;                 // b*16 + chunk
    int i  = threadIdx.x;                // 0..127
    int row = (bc >> 4)*SEQL + (bc & 15)*QC + i;
    float raw = g_zx[(size_t)row*DINPROJ + 1152] + dtb[0];
    float d = (raw > 20.f) ? raw : log1pf(expf(raw));
    __shared__ float sd[QC];
    __shared__ float sc[QC];
    sd[i] = d; __syncthreads();
    if (i == 0) {
        float A = -expf(alog[0]);
        float cacc = 0.f;
        for (int j = 0; j < QC; j++) { cacc += sd[j]*A; sc[j] = cacc; }
    }
    __syncthreads();
    g_dt[row] = d;
    g_cum[row] = sc[i];
}

// ---------------- chunk state: S[bc][n][p] = sum_i exp(cl-cum_i)*dt_i*B_i[n]*x_i[p]
__global__ __launch_bounds__(256) void k_S() {
    int bc = blockIdx.x;                 // 0..127
    int pt = blockIdx.y;                 // 0..3 -> p0 = pt*128
    int rowbase = (bc >> 4)*SEQL + (bc & 15)*QC;
    float cl = g_cum[rowbase + QC - 1];
    __shared__ __align__(16) float Bw[16][64];
    __shared__ __align__(16) float Xs[16][128];
    int tid = threadIdx.x;
    int nt = tid >> 4, ptg = tid & 15;   // n rows nt*4..+4; p = ptg*4 + q*64
    float acc[4][8];
    #pragma unroll
    for (int a = 0; a < 4; a++)
        #pragma unroll
        for (int b = 0; b < 8; b++) acc[a][b] = 0.f;

    // loader indices (each thread same row for its 4 B elems / 8 X elems)
    int eb = tid*4; int bii = eb >> 6, bn0 = eb & 63;
    int ex = tid*8; int xii = ex >> 7, xp0 = ex & 127;

    for (int i0 = 0; i0 < QC; i0 += 16) {
        int rb = rowbase + i0 + bii;
        float coef = expf(cl - g_cum[rb]) * g_dt[rb];
        #pragma unroll
        for (int j = 0; j < 4; j++)
            Bw[bii][bn0+j] = coef * g_xbc[(size_t)rb*CONVDIM + DINNER + bn0 + j];
        int rx = rowbase + i0 + xii;
        #pragma unroll
        for (int j = 0; j < 8; j++)
            Xs[xii][xp0+j] = g_xbc[(size_t)rx*CONVDIM + pt*128 + xp0 + j];
        __syncthreads();
        #pragma unroll
        for (int kk = 0; kk < 16; kk++) {
            float4 av = *(const float4*)&Bw[kk][nt*4];
            float a[4] = {av.x, av.y, av.z, av.w};
            #pragma unroll
            for (int q = 0; q < 2; q++) {
                float4 xv = *(const float4*)&Xs[kk][ptg*4 + q*64];
                #pragma unroll
                for (int nn = 0; nn < 4; nn++) {
                    acc[nn][q*4+0] += a[nn]*xv.x;
                    acc[nn][q*4+1] += a[nn]*xv.y;
                    acc[nn][q*4+2] += a[nn]*xv.z;
                    acc[nn][q*4+3] += a[nn]*xv.w;
                }
            }
        }
        __syncthreads();
    }
    #pragma unroll
    for (int nn = 0; nn < 4; nn++) {
        int n = nt*4 + nn;
        #pragma unroll
        for (int q = 0; q < 2; q++) {
            float4 st = make_float4(acc[nn][q*4], acc[nn][q*4+1], acc[nn][q*4+2], acc[nn][q*4+3]);
            *(float4*)&g_S[((size_t)bc*DSTATE + n)*DINNER + pt*128 + ptg*4 + q*64] = st;
        }
    }
}

// ---------------- chunk-boundary recurrence: Hstart[c] = dec_{c-1}*Hstart[c-1]+S[c-1]
__global__ __launch_bounds__(256) void k_H() {
    int b = blockIdx.x, ps = blockIdx.y;     // 8 x 8
    int tid = threadIdx.x;
    int n = tid >> 2;
    int p0 = ps*64 + (tid & 3)*16;
    float h[16];
    #pragma unroll
    for (int q = 0; q < 16; q++) h[q] = 0.f;
    for (int c = 0; c < NCH; c++) {
        size_t base = ((size_t)(b*NCH + c)*DSTATE + n)*DINNER + p0;
        #pragma unroll
        for (int q = 0; q < 4; q++)
            *(float4*)&g_H[base + q*4] = make_float4(h[q*4], h[q*4+1], h[q*4+2], h[q*4+3]);
        float dec = expf(g_cum[b*SEQL + c*QC + QC - 1]);
        #pragma unroll
        for (int q = 0; q < 4; q++) {
            float4 s4 = *(const float4*)&g_S[base + q*4];
            h[q*4+0] = h[q*4+0]*dec + s4.x;
            h[q*4+1] = h[q*4+1]*dec + s4.y;
            h[q*4+2] = h[q*4+2]*dec + s4.z;
            h[q*4+3] = h[q*4+3]*dec + s4.w;
        }
    }
}

// ---------------- fused Y: intra + inter + D*x, then gate (silu(z)) + rmsnorm ----
__global__ __launch_bounds__(256) void k_Y(const float* __restrict__ dparam,
                                           const float* __restrict__ ngw) {
    int bc = blockIdx.x;                 // 0..127
    int tt = blockIdx.y;                 // 0..7 -> rows i0..i0+15
    int c  = bc & 15;
    int rowbase = (bc >> 4)*SEQL + c*QC;
    int i0 = tt*16;
    __shared__ __align__(16) float Ball[128][65];   // also reused as stage[16][512]
    __shared__ float Cloc[16][64];
    __shared__ float Msh[16][128];
    __shared__ float scum[128], sdt[128], E[16];
    __shared__ float red[16][16];
    float* stage = &Ball[0][0];

    int tid = threadIdx.x;
    // load cum/dt for chunk
    if (tid < 128) { scum[tid] = g_cum[rowbase + tid]; sdt[tid] = g_dt[rowbase + tid]; }
    // load C rows (the 16 output rows)
    #pragma unroll
    for (int j = 0; j < 4; j++) {
        int e = j*256 + tid; int ii = e >> 6, n = e & 63;
        Cloc[ii][n] = g_xbc[(size_t)(rowbase+i0+ii)*CONVDIM + DINNER + DSTATE + n];
    }
    // load all 128 B rows
    #pragma unroll
    for (int j = 0; j < 32; j++) {
        int e = j*256 + tid; int ii = e >> 6, n = e & 63;
        Ball[ii][n] = g_xbc[(size_t)(rowbase+ii)*CONVDIM + DINNER + n];
    }
    __syncthreads();
    if (tid < 16) E[tid] = expf(scum[i0 + tid]);
    // M[i][s] = (s<=i0+i) ? exp(cum_i - cum_s)*dt_s*(C_i . B_s) : 0 ; diag += D
    float dpv = dparam[0];
    #pragma unroll
    for (int j = 0; j < 8; j++) {
        int e = j*256 + tid; int i = e >> 7, s = e & 127;
        float m = 0.f;
        if (s <= i0 + i) {
            float dot = 0.f;
            #pragma unroll
            for (int n = 0; n < 64; n++) dot += Cloc[i][n]*Ball[s][n];
            m = expf(scum[i0+i] - scum[s]) * sdt[s] * dot;
            if (s == i0 + i) m += dpv;
        }
        Msh[i][s] = m;
    }
    __syncthreads();   // everyone done with Ball; stage reuse is now safe

    int lt = tid >> 4, pg = tid & 15;    // row lt, p = pg*4 + q*64 (q<8)
    int row_t = rowbase + i0 + lt;
    float acc[32];
    #pragma unroll
    for (int q = 0; q < 32; q++) acc[q] = 0.f;

    // ---- intra-chunk (only s-chunks <= tt contribute) ----
    for (int ks = 0; ks <= tt; ks++) {
        #pragma unroll
        for (int j = 0; j < 32; j++) {
            int e = j*256 + tid; int si = e >> 9, p = e & 511;
            stage[si*512 + p] = g_xbc[(size_t)(rowbase + ks*16 + si)*CONVDIM + p];
        }
        __syncthreads();
        for (int si = 0; si < 16; si++) {
            float m = Msh[lt][ks*16 + si];
            if (m != 0.f) {
                const float4* xs = (const float4*)(stage + si*512 + pg*4);
                #pragma unroll
                for (int q = 0; q < 8; q++) {
                    float4 v = xs[q*16];
                    acc[q*4+0] += m*v.x; acc[q*4+1] += m*v.y;
                    acc[q*4+2] += m*v.z; acc[q*4+3] += m*v.w;
                }
            }
        }
        __syncthreads();
    }

    // ---- inter-chunk: acc += E[lt] * C_lt[n] * Hstart[n][p] ----
    if (c > 0) {
        float Ev = E[lt];
        for (int kh = 0; kh < 4; kh++) {
            #pragma unroll
            for (int j = 0; j < 32; j++) {
                int e = j*256 + tid; int ni = e >> 9, p = e & 511;
                stage[ni*512 + p] = g_H[((size_t)bc*DSTATE + kh*16 + ni)*DINNER + p];
            }
            __syncthreads();
            for (int ni = 0; ni < 16; ni++) {
                float cv = Cloc[lt][kh*16 + ni] * Ev;
                const float4* hs = (const float4*)(stage + ni*512 + pg*4);
                #pragma unroll
                for (int q = 0; q < 8; q++) {
                    float4 v = hs[q*16];
                    acc[q*4+0] += cv*v.x; acc[q*4+1] += cv*v.y;
                    acc[q*4+2] += cv*v.z; acc[q*4+3] += cv*v.w;
                }
            }
            __syncthreads();
        }
    }

    // ---- gate with silu(z), rmsnorm over 512, scale by ngw ----
    #pragma unroll
    for (int j = 0; j < 32; j++) {
        int e = j*256 + tid; int ti = e >> 9, p = e & 511;
        stage[ti*512 + p] = g_zx[(size_t)(rowbase + i0 + ti)*DINPROJ + p];
    }
    __syncthreads();
    float ssum = 0.f;
    #pragma unroll
    for (int q = 0; q < 8; q++) {
        float4 zv = *(const float4*)(stage + lt*512 + pg*4 + q*64);
        float z[4] = {zv.x, zv.y, zv.z, zv.w};
        #pragma unroll
        for (int k = 0; k < 4; k++) {
            float sg = z[k] / (1.f + expf(-z[k]));
            float gv = acc[q*4+k]*sg;
            acc[q*4+k] = gv;
            ssum += gv*gv;
        }
    }
    red[lt][pg] = ssum; __syncthreads();
    float tot = 0.f;
    #pragma unroll
    for (int k = 0; k < 16; k++) tot += red[lt][k];
    float rs = rsqrtf(tot*(1.f/DINNER) + 1e-5f);
    #pragma unroll
    for (int q = 0; q < 8; q++) {
        float4 gw = *(const float4*)&ngw[pg*4 + q*64];
        float4 o;
        o.x = acc[q*4+0]*rs*gw.x; o.y = acc[q*4+1]*rs*gw.y;
        o.z = acc[q*4+2]*rs*gw.z; o.w = acc[q*4+3]*rs*gw.w;
        *(float4*)&g_y[(size_t)row_t*DINNER + pg*4 + q*64] = o;
    }
}

// ---------------- final: residual + last-layer out, rmsnorm, logits (last token)
__global__ __launch_bounds__(256) void k_final(const float* __restrict__ nfw,
                                               const float* __restrict__ embed,
                                               float* __restrict__ out) {
    int b = blockIdx.x, t = threadIdx.x;
    int row = b*SEQL + SEQL - 1;
    float v = g_res[row*DMODEL + t] + g_hid[row*DMODEL + t];
    __shared__ float fin[256];
    __shared__ float sred[256];
    sred[t] = v*v; __syncthreads();
    #pragma unroll
    for (int s = 128; s > 0; s >>= 1) {
        if (t < s) sred[t] += sred[t+s];
        __syncthreads();
    }
    float rs = rsqrtf(sred[0]*(1.f/DMODEL) + 1e-5f);
    fin[t] = v*rs*nfw[t]; __syncthreads();
    if (t < 100) {
        float accv = 0.f;
        #pragma unroll 8
        for (int d = 0; d < DMODEL; d++) accv += fin[d]*embed[t*DMODEL + d];
        out[b*100 + t] = accv;
    }
}

// ---------------- launch ----------------
extern "C" void kernel_launch(void* const* d_in, const int* in_sizes, int n_in,
                              void* d_out, int out_size) {
    const int*   ids   = (const int*)  d_in[0];
    const float* embed = (const float*)d_in[1];
    const float* ipw   = (const float*)d_in[2];
    const float* cw    = (const float*)d_in[3];
    const float* cb    = (const float*)d_in[4];
    const float* dtb   = (const float*)d_in[5];
    const float* alog  = (const float*)d_in[6];
    const float* dpar  = (const float*)d_in[7];
    const float* ngw   = (const float*)d_in[8];
    const float* opw   = (const float*)d_in[9];
    const float* bnw   = (const float*)d_in[10];
    const float* nfw   = (const float*)d_in[11];
    float* out = (float*)d_out;

    k_embed<<<ROWS, 256>>>(ids, embed);
    for (int L = 0; L < 4; L++) {
        k_resnorm<<<ROWS, 256>>>(bnw + L*DMODEL, L > 0);
        sgemm_nt<<<dim3((DINPROJ + 63)/64, ROWS/128), 256>>>(0, ipw + (size_t)L*DINPROJ*DMODEL,
                                                             ROWS, DINPROJ, DMODEL);
        k_conv<<<(ROWS*CONVDIM + 255)/256, 256>>>(cw + L*CONVDIM*4, cb + L*CONVDIM);
        k_dtcum<<<BATCH*NCH, 128>>>(dtb + L, alog + L);
        k_S<<<dim3(BATCH*NCH, 4), 256>>>();
        k_H<<<dim3(BATCH, 8), 256>>>();
        k_Y<<<dim3(BATCH*NCH, 8), 256>>>(dpar + L, ngw + L*DINNER);
        sgemm_nt<<<dim3(DMODEL/64, ROWS/128), 256>>>(1, opw + (size_t)L*DMODEL*DINNER,
                                                     ROWS, DMODEL, DINNER);
    }
    k_final<<<BATCH, 256>>>(nfw, embed, out);
}

// round 4
// speedup vs baseline: 1.0904x; 1.0904x over previous
#include <cuda_runtime.h>
#include <cuda_bf16.h>
#include <math.h>
#include <stdint.h>

#define BATCH 8
#define SEQL 2048
#define ROWS (BATCH*SEQL)     // 16384
#define DMODEL 256
#define DINNER 512
#define DSTATE 64
#define CONVDIM 640
#define DINPROJ 1153
#define ZSTRIDE 1280          // padded in_proj output stride (10 tiles x 128)
#define QC 128                // chunk length
#define NCH (SEQL/QC)         // 16 chunks

// ---------------- scratch (device globals; no allocation allowed) ----------
__device__ float g_res[ROWS*DMODEL];
__device__ float g_hid[ROWS*DMODEL];
__device__ float g_hn [ROWS*DMODEL];
__device__ float g_zx [(size_t)ROWS*ZSTRIDE];
__device__ float g_xbc[ROWS*CONVDIM];
__device__ float g_y  [ROWS*DINNER];
__device__ float g_dt [ROWS];
__device__ float g_cum[ROWS];
__device__ float g_S[BATCH*NCH*DSTATE*DINNER];
__device__ float g_H[BATCH*NCH*DSTATE*DINNER];

__device__ __forceinline__ uint32_t smem_to_u32(const void* p) {
    uint32_t a;
    asm("{ .reg .u64 t; cvta.to.shared.u64 t, %1; cvt.u32.u64 %0, t; }" : "=r"(a) : "l"(p));
    return a;
}

// ---------------- embed gather ----------------
__global__ __launch_bounds__(256) void k_embed(const int* __restrict__ ids,
                                               const float* __restrict__ embed) {
    int row = blockIdx.x, t = threadIdx.x;
    g_res[row*DMODEL + t] = embed[ids[row]*DMODEL + t];
}

// ---------------- residual add + rmsnorm -> g_hn ----------------
__global__ __launch_bounds__(256) void k_resnorm(const float* __restrict__ w, int add) {
    int row = blockIdx.x, t = threadIdx.x;
    float v = g_res[row*DMODEL + t];
    if (add) { v += g_hid[row*DMODEL + t]; g_res[row*DMODEL + t] = v; }
    __shared__ float sred[256];
    sred[t] = v*v; __syncthreads();
    #pragma unroll
    for (int s = 128; s > 0; s >>= 1) {
        if (t < s) sred[t] += sred[t+s];
        __syncthreads();
    }
    float rs = rsqrtf(sred[0]*(1.f/DMODEL) + 1e-5f);
    g_hn[row*DMODEL + t] = v * rs * w[t];
}

// =================== bf16 mma.sync GEMM: C[M,N] = A[M,K] * B[N,K]^T ===============
// fp32 inputs, hi/lo bf16 split, 3-term MMA. Generic PTX (no sm_103a features).
// Block tile 128x128, 8 warps of 64x32, K-tile 32, 2-stage SMEM.
#define KT 32
#define ASTRIDE 40                       // bf16 elements per row (32 + 8 pad)
#define ARR_BYTES (128*ASTRIDE*2)        // 10240
#define STAGE_BYTES (4*ARR_BYTES)        // Ahi,Alo,Bhi,Blo = 40KB
#define GEMM_SMEM (2*STAGE_BYTES)        // 80KB

#define LDM4(r, addr) \
    asm volatile("ldmatrix.sync.aligned.m8n8.x4.shared.b16 {%0,%1,%2,%3}, [%4];" \
        : "=r"((r)[0]), "=r"((r)[1]), "=r"((r)[2]), "=r"((r)[3]) : "r"(addr))

#define MMA16816(c, a, b0, b1) \
    asm volatile("mma.sync.aligned.m16n8k16.row.col.f32.bf16.bf16.f32 " \
        "{%0,%1,%2,%3}, {%4,%5,%6,%7}, {%8,%9}, {%0,%1,%2,%3};" \
        : "+f"((c)[0]), "+f"((c)[1]), "+f"((c)[2]), "+f"((c)[3]) \
        : "r"((a)[0]), "r"((a)[1]), "r"((a)[2]), "r"((a)[3]), "r"(b0), "r"(b1))

__device__ __forceinline__ void cvt_hilo(float4 v, uint2& hi, uint2& lo) {
    __nv_bfloat162 h0 = __floats2bfloat162_rn(v.x, v.y);
    __nv_bfloat162 h1 = __floats2bfloat162_rn(v.z, v.w);
    float rx = v.x - __bfloat162float(__low2bfloat16(h0));
    float ry = v.y - __bfloat162float(__high2bfloat16(h0));
    float rz = v.z - __bfloat162float(__low2bfloat16(h1));
    float rw = v.w - __bfloat162float(__high2bfloat16(h1));
    __nv_bfloat162 l0 = __floats2bfloat162_rn(rx, ry);
    __nv_bfloat162 l1 = __floats2bfloat162_rn(rz, rw);
    hi = make_uint2(*(uint32_t*)&h0, *(uint32_t*)&h1);
    lo = make_uint2(*(uint32_t*)&l0, *(uint32_t*)&l1);
}

__global__ __launch_bounds__(256, 1) void gemm_bf3(int which, const float* __restrict__ Bw,
                                                   int K, int NB, int ldc) {
    extern __shared__ char smem[];
    const float* A; float* C;
    if (which == 0) { A = g_hn; C = g_zx; } else { A = g_y; C = g_hid; }

    uint32_t sb = smem_to_u32(smem);
    int tid = threadIdx.x;
    int wid = tid >> 5, lane = tid & 31;
    int m0 = blockIdx.y * 128;
    int n0 = blockIdx.x * 128;
    int wm = wid >> 2, wn = wid & 3;       // warp tile: rows wm*64, cols wn*32
    int nkt = K / KT;

    float c[4][4][4];
    #pragma unroll
    for (int i = 0; i < 4; i++)
        #pragma unroll
        for (int j = 0; j < 4; j++)
            #pragma unroll
            for (int q = 0; q < 4; q++) c[i][j][q] = 0.f;

    // ldmatrix per-lane byte offsets
    uint32_t a_off = (uint32_t)((lane & 15)*(ASTRIDE*2) + (lane >> 4)*16);
    uint32_t b_off = (uint32_t)(((lane & 7) + ((lane >> 4) << 3))*(ASTRIDE*2) + ((lane >> 3) & 1)*16);

    // loader indices: 1024 float4 per operand tile -> 4 per thread
    int lrow = -1, lc4 = 0;

    for (int kt = 0; kt < nkt; kt++) {
        int st = kt & 1;
        uint32_t base = sb + st*STAGE_BYTES;
        uint32_t ahi = base, alo = base + ARR_BYTES;
        uint32_t bhi = base + 2*ARR_BYTES, blo = base + 3*ARR_BYTES;
        int k0 = kt*KT;

        // ---- load + convert A,B tiles (global fp32 -> smem bf16 hi/lo) ----
        #pragma unroll
        for (int j = 0; j < 4; j++) {
            int e = j*256 + tid;
            lrow = e >> 3; lc4 = e & 7;
            uint32_t soff = (uint32_t)(lrow*(ASTRIDE*2) + lc4*8);
            float4 va = *(const float4*)&A[(size_t)(m0+lrow)*K + k0 + lc4*4];
            uint2 hi, lo;
            cvt_hilo(va, hi, lo);
            asm volatile("st.shared.v2.b32 [%0], {%1,%2};" :: "r"(ahi+soff), "r"(hi.x), "r"(hi.y) : "memory");
            asm volatile("st.shared.v2.b32 [%0], {%1,%2};" :: "r"(alo+soff), "r"(lo.x), "r"(lo.y) : "memory");
            int nrow = n0 + lrow;
            float4 vb = make_float4(0.f,0.f,0.f,0.f);
            if (nrow < NB) vb = *(const float4*)&Bw[(size_t)nrow*K + k0 + lc4*4];
            cvt_hilo(vb, hi, lo);
            asm volatile("st.shared.v2.b32 [%0], {%1,%2};" :: "r"(bhi+soff), "r"(hi.x), "r"(hi.y) : "memory");
            asm volatile("st.shared.v2.b32 [%0], {%1,%2};" :: "r"(blo+soff), "r"(lo.x), "r"(lo.y) : "memory");
        }
        __syncthreads();

        // ---- mma over the 2 k16 halves ----
        #pragma unroll
        for (int h = 0; h < 2; h++) {
            uint32_t kh = h*32;  // 16 bf16 = 32 bytes
            uint32_t Ah[4][4], Al[4][4], Bh[2][4], Bl[2][4];
            #pragma unroll
            for (int mf = 0; mf < 4; mf++) {
                uint32_t rb = (uint32_t)((wm*64 + mf*16)*(ASTRIDE*2)) + kh + a_off;
                LDM4(Ah[mf], ahi + rb);
                LDM4(Al[mf], alo + rb);
            }
            #pragma unroll
            for (int g = 0; g < 2; g++) {
                uint32_t rb = (uint32_t)((wn*32 + g*16)*(ASTRIDE*2)) + kh + b_off;
                LDM4(Bh[g], bhi + rb);
                LDM4(Bl[g], blo + rb);
            }
            #pragma unroll
            for (int mf = 0; mf < 4; mf++) {
                #pragma unroll
                for (int nf = 0; nf < 4; nf++) {
                    int g = nf >> 1, o = (nf & 1)*2;
                    MMA16816(c[mf][nf], Ah[mf], Bh[g][o], Bh[g][o+1]);
                    MMA16816(c[mf][nf], Al[mf], Bh[g][o], Bh[g][o+1]);
                    MMA16816(c[mf][nf], Ah[mf], Bl[g][o], Bl[g][o+1]);
                }
            }
        }
        __syncthreads();
    }

    // ---- epilogue: direct stores (float2 pairs) ----
    #pragma unroll
    for (int mf = 0; mf < 4; mf++) {
        int r0 = m0 + wm*64 + mf*16 + (lane >> 2);
        #pragma unroll
        for (int nf = 0; nf < 4; nf++) {
            int col = n0 + wn*32 + nf*8 + (lane & 3)*2;
            *(float2*)&C[(size_t)r0*ldc + col]     = make_float2(c[mf][nf][0], c[mf][nf][1]);
            *(float2*)&C[(size_t)(r0+8)*ldc + col] = make_float2(c[mf][nf][2], c[mf][nf][3]);
        }
    }
}

// ---------------- depthwise causal conv (window 4) + silu ----------------
__global__ __launch_bounds__(256) void k_conv(const float* __restrict__ cw,
                                              const float* __restrict__ cb) {
    int idx = blockIdx.x*256 + threadIdx.x;
    if (idx >= ROWS*CONVDIM) return;
    int c = idx % CONVDIM, row = idx / CONVDIM;
    int t = row & (SEQL-1);
    float w0 = cw[c*4+0], w1 = cw[c*4+1], w2 = cw[c*4+2], w3 = cw[c*4+3];
    float acc = cb[c];
    const float* base = g_zx + (size_t)row*ZSTRIDE + DINNER + c;
    if (t >= 3) acc += base[-3*ZSTRIDE]*w0;
    if (t >= 2) acc += base[-2*ZSTRIDE]*w1;
    if (t >= 1) acc += base[-1*ZSTRIDE]*w2;
    acc += base[0]*w3;
    g_xbc[idx] = acc / (1.f + expf(-acc));   // silu
}

// ---------------- dt = softplus(raw + dtb); per-chunk inclusive cumsum of dt*A ----
__global__ __launch_bounds__(128) void k_dtcum(const float* __restrict__ dtb,
                                               const float* __restrict__ alog) {
    int bc = blockIdx.x;
    int i  = threadIdx.x;
    int row = (bc >> 4)*SEQL + (bc & 15)*QC + i;
    float raw = g_zx[(size_t)row*ZSTRIDE + 1152] + dtb[0];
    float d = (raw > 20.f) ? raw : log1pf(expf(raw));
    __shared__ float sd[QC];
    __shared__ float sc[QC];
    sd[i] = d; __syncthreads();
    if (i == 0) {
        float A = -expf(alog[0]);
        float cacc = 0.f;
        for (int j = 0; j < QC; j++) { cacc += sd[j]*A; sc[j] = cacc; }
    }
    __syncthreads();
    g_dt[row] = d;
    g_cum[row] = sc[i];
}

// ---------------- chunk state: S[bc][n][p] = sum_i exp(cl-cum_i)*dt_i*B_i[n]*x_i[p]
__global__ __launch_bounds__(256) void k_S() {
    int bc = blockIdx.x;
    int pt = blockIdx.y;
    int rowbase = (bc >> 4)*SEQL + (bc & 15)*QC;
    float cl = g_cum[rowbase + QC - 1];
    __shared__ __align__(16) float Bw[16][64];
    __shared__ __align__(16) float Xs[16][128];
    int tid = threadIdx.x;
    int nt = tid >> 4, ptg = tid & 15;
    float acc[4][8];
    #pragma unroll
    for (int a = 0; a < 4; a++)
        #pragma unroll
        for (int b = 0; b < 8; b++) acc[a][b] = 0.f;

    int eb = tid*4; int bii = eb >> 6, bn0 = eb & 63;
    int ex = tid*8; int xii = ex >> 7, xp0 = ex & 127;

    for (int i0 = 0; i0 < QC; i0 += 16) {
        int rb = rowbase + i0 + bii;
        float coef = expf(cl - g_cum[rb]) * g_dt[rb];
        #pragma unroll
        for (int j = 0; j < 4; j++)
            Bw[bii][bn0+j] = coef * g_xbc[(size_t)rb*CONVDIM + DINNER + bn0 + j];
        int rx = rowbase + i0 + xii;
        #pragma unroll
        for (int j = 0; j < 8; j++)
            Xs[xii][xp0+j] = g_xbc[(size_t)rx*CONVDIM + pt*128 + xp0 + j];
        __syncthreads();
        #pragma unroll
        for (int kk = 0; kk < 16; kk++) {
            float4 av = *(const float4*)&Bw[kk][nt*4];
            float a[4] = {av.x, av.y, av.z, av.w};
            #pragma unroll
            for (int q = 0; q < 2; q++) {
                float4 xv = *(const float4*)&Xs[kk][ptg*4 + q*64];
                #pragma unroll
                for (int nn = 0; nn < 4; nn++) {
                    acc[nn][q*4+0] += a[nn]*xv.x;
                    acc[nn][q*4+1] += a[nn]*xv.y;
                    acc[nn][q*4+2] += a[nn]*xv.z;
                    acc[nn][q*4+3] += a[nn]*xv.w;
                }
            }
        }
        __syncthreads();
    }
    #pragma unroll
    for (int nn = 0; nn < 4; nn++) {
        int n = nt*4 + nn;
        #pragma unroll
        for (int q = 0; q < 2; q++) {
            float4 st = make_float4(acc[nn][q*4], acc[nn][q*4+1], acc[nn][q*4+2], acc[nn][q*4+3]);
            *(float4*)&g_S[((size_t)bc*DSTATE + n)*DINNER + pt*128 + ptg*4 + q*64] = st;
        }
    }
}

// ---------------- chunk-boundary recurrence ----------------
__global__ __launch_bounds__(256) void k_H() {
    int b = blockIdx.x, ps = blockIdx.y;
    int tid = threadIdx.x;
    int n = tid >> 2;
    int p0 = ps*64 + (tid & 3)*16;
    float h[16];
    #pragma unroll
    for (int q = 0; q < 16; q++) h[q] = 0.f;
    for (int c = 0; c < NCH; c++) {
        size_t base = ((size_t)(b*NCH + c)*DSTATE + n)*DINNER + p0;
        #pragma unroll
        for (int q = 0; q < 4; q++)
            *(float4*)&g_H[base + q*4] = make_float4(h[q*4], h[q*4+1], h[q*4+2], h[q*4+3]);
        float dec = expf(g_cum[b*SEQL + c*QC + QC - 1]);
        #pragma unroll
        for (int q = 0; q < 4; q++) {
            float4 s4 = *(const float4*)&g_S[base + q*4];
            h[q*4+0] = h[q*4+0]*dec + s4.x;
            h[q*4+1] = h[q*4+1]*dec + s4.y;
            h[q*4+2] = h[q*4+2]*dec + s4.z;
            h[q*4+3] = h[q*4+3]*dec + s4.w;
        }
    }
}

// ---------------- fused Y: intra + inter + D*x, gate, rmsnorm ----------------
__global__ __launch_bounds__(256) void k_Y(const float* __restrict__ dparam,
                                           const float* __restrict__ ngw) {
    int bc = blockIdx.x;
    int tt = blockIdx.y;
    int c  = bc & 15;
    int rowbase = (bc >> 4)*SEQL + c*QC;
    int i0 = tt*16;
    __shared__ __align__(16) float Ball[128][65];
    __shared__ float Cloc[16][64];
    __shared__ float Msh[16][128];
    __shared__ float scum[128], sdt[128], E[16];
    __shared__ float red[16][16];
    float* stage = &Ball[0][0];

    int tid = threadIdx.x;
    if (tid < 128) { scum[tid] = g_cum[rowbase + tid]; sdt[tid] = g_dt[rowbase + tid]; }
    #pragma unroll
    for (int j = 0; j < 4; j++) {
        int e = j*256 + tid; int ii = e >> 6, n = e & 63;
        Cloc[ii][n] = g_xbc[(size_t)(rowbase+i0+ii)*CONVDIM + DINNER + DSTATE + n];
    }
    #pragma unroll
    for (int j = 0; j < 32; j++) {
        int e = j*256 + tid; int ii = e >> 6, n = e & 63;
        Ball[ii][n] = g_xbc[(size_t)(rowbase+ii)*CONVDIM + DINNER + n];
    }
    __syncthreads();
    if (tid < 16) E[tid] = expf(scum[i0 + tid]);
    float dpv = dparam[0];
    #pragma unroll
    for (int j = 0; j < 8; j++) {
        int e = j*256 + tid; int i = e >> 7, s = e & 127;
        float m = 0.f;
        if (s <= i0 + i) {
            float dot = 0.f;
            #pragma unroll
            for (int n = 0; n < 64; n++) dot += Cloc[i][n]*Ball[s][n];
            m = expf(scum[i0+i] - scum[s]) * sdt[s] * dot;
            if (s == i0 + i) m += dpv;
        }
        Msh[i][s] = m;
    }
    __syncthreads();

    int lt = tid >> 4, pg = tid & 15;
    int row_t = rowbase + i0 + lt;
    float acc[32];
    #pragma unroll
    for (int q = 0; q < 32; q++) acc[q] = 0.f;

    for (int ks = 0; ks <= tt; ks++) {
        #pragma unroll
        for (int j = 0; j < 32; j++) {
            int e = j*256 + tid; int si = e >> 9, p = e & 511;
            stage[si*512 + p] = g_xbc[(size_t)(rowbase + ks*16 + si)*CONVDIM + p];
        }
        __syncthreads();
        for (int si = 0; si < 16; si++) {
            float m = Msh[lt][ks*16 + si];
            if (m != 0.f) {
                const float4* xs = (const float4*)(stage + si*512 + pg*4);
                #pragma unroll
                for (int q = 0; q < 8; q++) {
                    float4 v = xs[q*16];
                    acc[q*4+0] += m*v.x; acc[q*4+1] += m*v.y;
                    acc[q*4+2] += m*v.z; acc[q*4+3] += m*v.w;
                }
            }
        }
        __syncthreads();
    }

    if (c > 0) {
        float Ev = E[lt];
        for (int kh = 0; kh < 4; kh++) {
            #pragma unroll
            for (int j = 0; j < 32; j++) {
                int e = j*256 + tid; int ni = e >> 9, p = e & 511;
                stage[ni*512 + p] = g_H[((size_t)bc*DSTATE + kh*16 + ni)*DINNER + p];
            }
            __syncthreads();
            for (int ni = 0; ni < 16; ni++) {
                float cv = Cloc[lt][kh*16 + ni] * Ev;
                const float4* hs = (const float4*)(stage + ni*512 + pg*4);
                #pragma unroll
                for (int q = 0; q < 8; q++) {
                    float4 v = hs[q*16];
                    acc[q*4+0] += cv*v.x; acc[q*4+1] += cv*v.y;
                    acc[q*4+2] += cv*v.z; acc[q*4+3] += cv*v.w;
                }
            }
            __syncthreads();
        }
    }

    #pragma unroll
    for (int j = 0; j < 32; j++) {
        int e = j*256 + tid; int ti = e >> 9, p = e & 511;
        stage[ti*512 + p] = g_zx[(size_t)(rowbase + i0 + ti)*ZSTRIDE + p];
    }
    __syncthreads();
    float ssum = 0.f;
    #pragma unroll
    for (int q = 0; q < 8; q++) {
        float4 zv = *(const float4*)(stage + lt*512 + pg*4 + q*64);
        float z[4] = {zv.x, zv.y, zv.z, zv.w};
        #pragma unroll
        for (int k = 0; k < 4; k++) {
            float sg = z[k] / (1.f + expf(-z[k]));
            float gv = acc[q*4+k]*sg;
            acc[q*4+k] = gv;
            ssum += gv*gv;
        }
    }
    red[lt][pg] = ssum; __syncthreads();
    float tot = 0.f;
    #pragma unroll
    for (int k = 0; k < 16; k++) tot += red[lt][k];
    float rs = rsqrtf(tot*(1.f/DINNER) + 1e-5f);
    #pragma unroll
    for (int q = 0; q < 8; q++) {
        float4 gw = *(const float4*)&ngw[pg*4 + q*64];
        float4 o;
        o.x = acc[q*4+0]*rs*gw.x; o.y = acc[q*4+1]*rs*gw.y;
        o.z = acc[q*4+2]*rs*gw.z; o.w = acc[q*4+3]*rs*gw.w;
        *(float4*)&g_y[(size_t)row_t*DINNER + pg*4 + q*64] = o;
    }
}

// ---------------- final ----------------
__global__ __launch_bounds__(256) void k_final(const float* __restrict__ nfw,
                                               const float* __restrict__ embed,
                                               float* __restrict__ out) {
    int b = blockIdx.x, t = threadIdx.x;
    int row = b*SEQL + SEQL - 1;
    float v = g_res[row*DMODEL + t] + g_hid[row*DMODEL + t];
    __shared__ float fin[256];
    __shared__ float sred[256];
    sred[t] = v*v; __syncthreads();
    #pragma unroll
    for (int s = 128; s > 0; s >>= 1) {
        if (t < s) sred[t] += sred[t+s];
        __syncthreads();
    }
    float rs = rsqrtf(sred[0]*(1.f/DMODEL) + 1e-5f);
    fin[t] = v*rs*nfw[t]; __syncthreads();
    if (t < 100) {
        float accv = 0.f;
        #pragma unroll 8
        for (int d = 0; d < DMODEL; d++) accv += fin[d]*embed[t*DMODEL + d];
        out[b*100 + t] = accv;
    }
}

// ---------------- launch ----------------
extern "C" void kernel_launch(void* const* d_in, const int* in_sizes, int n_in,
                              void* d_out, int out_size) {
    const int*   ids   = (const int*)  d_in[0];
    const float* embed = (const float*)d_in[1];
    const float* ipw   = (const float*)d_in[2];
    const float* cw    = (const float*)d_in[3];
    const float* cb    = (const float*)d_in[4];
    const float* dtb   = (const float*)d_in[5];
    const float* alog  = (const float*)d_in[6];
    const float* dpar  = (const float*)d_in[7];
    const float* ngw   = (const float*)d_in[8];
    const float* opw   = (const float*)d_in[9];
    const float* bnw   = (const float*)d_in[10];
    const float* nfw   = (const float*)d_in[11];
    float* out = (float*)d_out;

    cudaFuncSetAttribute(gemm_bf3, cudaFuncAttributeMaxDynamicSharedMemorySize, GEMM_SMEM);

    k_embed<<<ROWS, 256>>>(ids, embed);
    for (int L = 0; L < 4; L++) {
        k_resnorm<<<ROWS, 256>>>(bnw + L*DMODEL, L > 0);
        gemm_bf3<<<dim3(10, ROWS/128), 256, GEMM_SMEM>>>(0, ipw + (size_t)L*DINPROJ*DMODEL,
                                                         DMODEL, DINPROJ, ZSTRIDE);
        k_conv<<<(ROWS*CONVDIM + 255)/256, 256>>>(cw + L*CONVDIM*4, cb + L*CONVDIM);
        k_dtcum<<<BATCH*NCH, 128>>>(dtb + L, alog + L);
        k_S<<<dim3(BATCH*NCH, 4), 256>>>();
        k_H<<<dim3(BATCH, 8), 256>>>();
        k_Y<<<dim3(BATCH*NCH, 8), 256>>>(dpar + L, ngw + L*DINNER);
        gemm_bf3<<<dim3(2, ROWS/128), 256, GEMM_SMEM>>>(1, opw + (size_t)L*DMODEL*DINNER,
                                                        DINNER, DMODEL, DMODEL);
    }
    k_final<<<BATCH, 256>>>(nfw, embed, out);
}

// round 9
// speedup vs baseline: 1.9587x; 1.7964x over previous
#include <cuda_runtime.h>
#include <cuda_bf16.h>
#include <math.h>
#include <stdint.h>

#define BATCH 8
#define SEQL 2048
#define ROWS (BATCH*SEQL)     // 16384
#define DMODEL 256
#define DINNER 512
#define DSTATE 64
#define CONVDIM 640
#define DINPROJ 1153
#define ZSTRIDE 1280
#define QC 128
#define NCH (SEQL/QC)         // 16

// ---------------- scratch ----------------
__device__ float g_res[ROWS*DMODEL];
__device__ float g_hid[ROWS*DMODEL];
__device__ float g_hn [ROWS*DMODEL];
__device__ float g_zx [(size_t)ROWS*ZSTRIDE];
__device__ float g_xbc[ROWS*CONVDIM];
__device__ float g_y  [ROWS*DINNER];
__device__ float g_dt [ROWS];
__device__ float g_cum[ROWS];
__device__ float g_S[BATCH*NCH*DSTATE*DINNER];
__device__ float g_H[BATCH*NCH*DSTATE*DINNER];
__device__ float g_M[(size_t)BATCH*NCH*QC*QC];   // 8MB, Mt[s][i] per chunk

__device__ __forceinline__ uint32_t smem_to_u32(const void* p) {
    uint32_t a;
    asm("{ .reg .u64 t; cvta.to.shared.u64 t, %1; cvt.u32.u64 %0, t; }" : "=r"(a) : "l"(p));
    return a;
}

// ---------------- probe (occupies launch slot 2 so gemm0 lands in the ncu slot)
__global__ void k_probe() { g_cum[0] = 0.f; }

// ---------------- embed gather ----------------
__global__ __launch_bounds__(256) void k_embed(const int* __restrict__ ids,
                                               const float* __restrict__ embed) {
    int row = blockIdx.x, t = threadIdx.x;
    g_res[row*DMODEL + t] = embed[ids[row]*DMODEL + t];
}

// ---------------- residual add + rmsnorm -> g_hn (shuffle reduction) --------
__global__ __launch_bounds__(256) void k_resnorm(const float* __restrict__ w, int add) {
    int row = blockIdx.x, t = threadIdx.x;
    float v = g_res[row*DMODEL + t];
    if (add) { v += g_hid[row*DMODEL + t]; g_res[row*DMODEL + t] = v; }
    float s = v*v;
    #pragma unroll
    for (int o = 16; o > 0; o >>= 1) s += __shfl_xor_sync(0xffffffffu, s, o);
    __shared__ float wred[8];
    if ((t & 31) == 0) wred[t >> 5] = s;
    __syncthreads();
    float tot = wred[0]+wred[1]+wred[2]+wred[3]+wred[4]+wred[5]+wred[6]+wred[7];
    float rs = rsqrtf(tot*(1.f/DMODEL) + 1e-5f);
    g_hn[row*DMODEL + t] = v * rs * w[t];
}

// =================== bf16 mma.sync GEMM (hi/lo 3-term) ===================
#define KT 32
#define ASTRIDE 40
#define ARR_BYTES (128*ASTRIDE*2)
#define STAGE_BYTES (4*ARR_BYTES)
#define GEMM_SMEM (2*STAGE_BYTES)

#define LDM4(r, addr) \
    asm volatile("ldmatrix.sync.aligned.m8n8.x4.shared.b16 {%0,%1,%2,%3}, [%4];" \
        : "=r"((r)[0]), "=r"((r)[1]), "=r"((r)[2]), "=r"((r)[3]) : "r"(addr))

#define MMA16816(c, a, b0, b1) \
    asm volatile("mma.sync.aligned.m16n8k16.row.col.f32.bf16.bf16.f32 " \
        "{%0,%1,%2,%3}, {%4,%5,%6,%7}, {%8,%9}, {%0,%1,%2,%3};" \
        : "+f"((c)[0]), "+f"((c)[1]), "+f"((c)[2]), "+f"((c)[3]) \
        : "r"((a)[0]), "r"((a)[1]), "r"((a)[2]), "r"((a)[3]), "r"(b0), "r"(b1))

__device__ __forceinline__ void cvt_hilo(float4 v, uint2& hi, uint2& lo) {
    __nv_bfloat162 h0 = __floats2bfloat162_rn(v.x, v.y);
    __nv_bfloat162 h1 = __floats2bfloat162_rn(v.z, v.w);
    float rx = v.x - __bfloat162float(__low2bfloat16(h0));
    float ry = v.y - __bfloat162float(__high2bfloat16(h0));
    float rz = v.z - __bfloat162float(__low2bfloat16(h1));
    float rw = v.w - __bfloat162float(__high2bfloat16(h1));
    __nv_bfloat162 l0 = __floats2bfloat162_rn(rx, ry);
    __nv_bfloat162 l1 = __floats2bfloat162_rn(rz, rw);
    hi = make_uint2(*(uint32_t*)&h0, *(uint32_t*)&h1);
    lo = make_uint2(*(uint32_t*)&l0, *(uint32_t*)&l1);
}

__global__ __launch_bounds__(256, 1) void gemm_bf3(int which, const float* __restrict__ Bw,
                                                   int K, int NB, int ldc) {
    extern __shared__ char smem[];
    const float* A; float* C;
    if (which == 0) { A = g_hn; C = g_zx; } else { A = g_y; C = g_hid; }

    uint32_t sb = smem_to_u32(smem);
    int tid = threadIdx.x;
    int wid = tid >> 5, lane = tid & 31;
    int m0 = blockIdx.y * 128;
    int n0 = blockIdx.x * 128;
    int wm = wid >> 2, wn = wid & 3;
    int nkt = K / KT;

    float c[4][4][4];
    #pragma unroll
    for (int i = 0; i < 4; i++)
        #pragma unroll
        for (int j = 0; j < 4; j++)
            #pragma unroll
            for (int q = 0; q < 4; q++) c[i][j][q] = 0.f;

    uint32_t a_off = (uint32_t)((lane & 15)*(ASTRIDE*2) + (lane >> 4)*16);
    uint32_t b_off = (uint32_t)(((lane & 7) + ((lane >> 4) << 3))*(ASTRIDE*2) + ((lane >> 3) & 1)*16);

    for (int kt = 0; kt < nkt; kt++) {
        int st = kt & 1;
        uint32_t base = sb + st*STAGE_BYTES;
        uint32_t ahi = base, alo = base + ARR_BYTES;
        uint32_t bhi = base + 2*ARR_BYTES, blo = base + 3*ARR_BYTES;
        int k0 = kt*KT;

        #pragma unroll
        for (int j = 0; j < 4; j++) {
            int e = j*256 + tid;
            int lrow = e >> 3, lc4 = e & 7;
            uint32_t soff = (uint32_t)(lrow*(ASTRIDE*2) + lc4*8);
            float4 va = *(const float4*)&A[(size_t)(m0+lrow)*K + k0 + lc4*4];
            uint2 hi, lo;
            cvt_hilo(va, hi, lo);
            asm volatile("st.shared.v2.b32 [%0], {%1,%2};" :: "r"(ahi+soff), "r"(hi.x), "r"(hi.y) : "memory");
            asm volatile("st.shared.v2.b32 [%0], {%1,%2};" :: "r"(alo+soff), "r"(lo.x), "r"(lo.y) : "memory");
            int nrow = n0 + lrow;
            float4 vb = make_float4(0.f,0.f,0.f,0.f);
            if (nrow < NB) vb = *(const float4*)&Bw[(size_t)nrow*K + k0 + lc4*4];
            cvt_hilo(vb, hi, lo);
            asm volatile("st.shared.v2.b32 [%0], {%1,%2};" :: "r"(bhi+soff), "r"(hi.x), "r"(hi.y) : "memory");
            asm volatile("st.shared.v2.b32 [%0], {%1,%2};" :: "r"(blo+soff), "r"(lo.x), "r"(lo.y) : "memory");
        }
        __syncthreads();

        #pragma unroll
        for (int h = 0; h < 2; h++) {
            uint32_t kh = h*32;
            uint32_t Ah[4][4], Al[4][4], Bh[2][4], Bl[2][4];
            #pragma unroll
            for (int mf = 0; mf < 4; mf++) {
                uint32_t rb = (uint32_t)((wm*64 + mf*16)*(ASTRIDE*2)) + kh + a_off;
                LDM4(Ah[mf], ahi + rb);
                LDM4(Al[mf], alo + rb);
            }
            #pragma unroll
            for (int g = 0; g < 2; g++) {
                uint32_t rb = (uint32_t)((wn*32 + g*16)*(ASTRIDE*2)) + kh + b_off;
                LDM4(Bh[g], bhi + rb);
                LDM4(Bl[g], blo + rb);
            }
            #pragma unroll
            for (int mf = 0; mf < 4; mf++) {
                #pragma unroll
                for (int nf = 0; nf < 4; nf++) {
                    int g = nf >> 1, o = (nf & 1)*2;
                    MMA16816(c[mf][nf], Ah[mf], Bh[g][o], Bh[g][o+1]);
                    MMA16816(c[mf][nf], Al[mf], Bh[g][o], Bh[g][o+1]);
                    MMA16816(c[mf][nf], Ah[mf], Bl[g][o], Bl[g][o+1]);
                }
            }
        }
        __syncthreads();
    }

    #pragma unroll
    for (int mf = 0; mf < 4; mf++) {
        int r0 = m0 + wm*64 + mf*16 + (lane >> 2);
        #pragma unroll
        for (int nf = 0; nf < 4; nf++) {
            int col = n0 + wn*32 + nf*8 + (lane & 3)*2;
            *(float2*)&C[(size_t)r0*ldc + col]     = make_float2(c[mf][nf][0], c[mf][nf][1]);
            *(float2*)&C[(size_t)(r0+8)*ldc + col] = make_float2(c[mf][nf][2], c[mf][nf][3]);
        }
    }
}

// ---------------- conv: 4 timesteps per thread, rolling window ----------------
__global__ __launch_bounds__(256) void k_conv(const float* __restrict__ cw,
                                              const float* __restrict__ cb) {
    int idx = blockIdx.x*256 + threadIdx.x;          // (ROWS/4)*CONVDIM threads
    if (idx >= (ROWS/4)*CONVDIM) return;
    int c  = idx % CONVDIM;
    int tg = idx / CONVDIM;
    int row0 = tg*4;
    int t0 = row0 & (SEQL-1);
    float w0 = cw[c*4+0], w1 = cw[c*4+1], w2 = cw[c*4+2], w3 = cw[c*4+3];
    float bias = cb[c];
    const float* base = g_zx + (size_t)row0*ZSTRIDE + DINNER + c;
    float v[7];
    #pragma unroll
    for (int j = 0; j < 3; j++)
        v[j] = (t0 + j >= 3) ? base[(j-3)*ZSTRIDE] : 0.f;
    #pragma unroll
    for (int j = 3; j < 7; j++)
        v[j] = base[(j-3)*ZSTRIDE];
    #pragma unroll
    for (int k = 0; k < 4; k++) {
        float acc = bias + v[k]*w0 + v[k+1]*w1 + v[k+2]*w2 + v[k+3]*w3;
        g_xbc[(size_t)(row0+k)*CONVDIM + c] = acc / (1.f + expf(-acc));
    }
}

// ---------------- k_M: dt softplus + cumsum + chunk M matrix (transposed) ----
#define MPAD 65
#define KM_SMEM ((2*QC*MPAD + 2*QC)*4)
__global__ __launch_bounds__(256) void k_M(const float* __restrict__ dtb,
                                           const float* __restrict__ alog,
                                           const float* __restrict__ dparam) {
    extern __shared__ float sm[];
    float* Bs   = sm;                    // [128][65]
    float* Cs   = Bs + QC*MPAD;          // [128][65]
    float* scum = Cs + QC*MPAD;          // [128]
    float* sdt  = scum + QC;             // [128]
    int bc = blockIdx.x;
    int tid = threadIdx.x;
    int rowbase = (bc >> 4)*SEQL + (bc & 15)*QC;

    if (tid < QC) {
        float raw = g_zx[(size_t)(rowbase+tid)*ZSTRIDE + 1152] + dtb[0];
        sdt[tid] = (raw > 20.f) ? raw : log1pf(expf(raw));
    }
    // load B,C
    #pragma unroll
    for (int j = 0; j < 32; j++) {
        int e = j*256 + tid; int ii = e >> 6, n = e & 63;
        const float* src = g_xbc + (size_t)(rowbase+ii)*CONVDIM + DINNER;
        Bs[ii*MPAD + n] = src[n];
        Cs[ii*MPAD + n] = src[DSTATE + n];
    }
    __syncthreads();
    if (tid == 0) {
        float A = -expf(alog[0]);
        float cacc = 0.f;
        for (int j = 0; j < QC; j++) { cacc += sdt[j]*A; scum[j] = cacc; }
    }
    __syncthreads();
    if (tid < QC) { g_dt[rowbase+tid] = sdt[tid]; g_cum[rowbase+tid] = scum[tid]; }

    int i  = tid >> 1;
    int s0 = (tid & 1)*64;
    float dpv = dparam[0];
    float ci  = scum[i];
    float* Mo = g_M + ((size_t)bc*QC)*QC;
    for (int sj = 0; sj < 64; sj++) {
        int s = s0 + sj;
        float m = 0.f;
        if (s <= i) {
            float dot = 0.f;
            #pragma unroll 16
            for (int n = 0; n < 64; n++) dot += Cs[i*MPAD+n]*Bs[s*MPAD+n];
            m = expf(ci - scum[s]) * sdt[s] * dot;
            if (s == i) m += dpv;
        }
        Mo[(size_t)s*QC + i] = m;   // transposed Mt[s][i]
    }
}

// ---------------- chunk state S (unchanged) ----------------
__global__ __launch_bounds__(256) void k_S() {
    int bc = blockIdx.x;
    int pt = blockIdx.y;
    int rowbase = (bc >> 4)*SEQL + (bc & 15)*QC;
    float cl = g_cum[rowbase + QC - 1];
    __shared__ __align__(16) float Bw[16][64];
    __shared__ __align__(16) float Xs[16][128];
    int tid = threadIdx.x;
    int nt = tid >> 4, ptg = tid & 15;
    float acc[4][8];
    #pragma unroll
    for (int a = 0; a < 4; a++)
        #pragma unroll
        for (int b = 0; b < 8; b++) acc[a][b] = 0.f;

    int eb = tid*4; int bii = eb >> 6, bn0 = eb & 63;
    int ex = tid*8; int xii = ex >> 7, xp0 = ex & 127;

    for (int i0 = 0; i0 < QC; i0 += 16) {
        int rb = rowbase + i0 + bii;
        float coef = expf(cl - g_cum[rb]) * g_dt[rb];
        #pragma unroll
        for (int j = 0; j < 4; j++)
            Bw[bii][bn0+j] = coef * g_xbc[(size_t)rb*CONVDIM + DINNER + bn0 + j];
        int rx = rowbase + i0 + xii;
        #pragma unroll
        for (int j = 0; j < 8; j++)
            Xs[xii][xp0+j] = g_xbc[(size_t)rx*CONVDIM + pt*128 + xp0 + j];
        __syncthreads();
        #pragma unroll
        for (int kk = 0; kk < 16; kk++) {
            float4 av = *(const float4*)&Bw[kk][nt*4];
            float a[4] = {av.x, av.y, av.z, av.w};
            #pragma unroll
            for (int q = 0; q < 2; q++) {
                float4 xv = *(const float4*)&Xs[kk][ptg*4 + q*64];
                #pragma unroll
                for (int nn = 0; nn < 4; nn++) {
                    acc[nn][q*4+0] += a[nn]*xv.x;
                    acc[nn][q*4+1] += a[nn]*xv.y;
                    acc[nn][q*4+2] += a[nn]*xv.z;
                    acc[nn][q*4+3] += a[nn]*xv.w;
                }
            }
        }
        __syncthreads();
    }
    #pragma unroll
    for (int nn = 0; nn < 4; nn++) {
        int n = nt*4 + nn;
        #pragma unroll
        for (int q = 0; q < 2; q++) {
            float4 st = make_float4(acc[nn][q*4], acc[nn][q*4+1], acc[nn][q*4+2], acc[nn][q*4+3]);
            *(float4*)&g_S[((size_t)bc*DSTATE + n)*DINNER + pt*128 + ptg*4 + q*64] = st;
        }
    }
}

// ---------------- chunk-boundary recurrence ----------------
__global__ __launch_bounds__(256) void k_H() {
    int b = blockIdx.x, ps = blockIdx.y;
    int tid = threadIdx.x;
    int n = tid >> 2;
    int p0 = ps*64 + (tid & 3)*16;
    float h[16];
    #pragma unroll
    for (int q = 0; q < 16; q++) h[q] = 0.f;
    for (int c = 0; c < NCH; c++) {
        size_t base = ((size_t)(b*NCH + c)*DSTATE + n)*DINNER + p0;
        #pragma unroll
        for (int q = 0; q < 4; q++)
            *(float4*)&g_H[base + q*4] = make_float4(h[q*4], h[q*4+1], h[q*4+2], h[q*4+3]);
        float dec = expf(g_cum[b*SEQL + c*QC + QC - 1]);
        #pragma unroll
        for (int q = 0; q < 4; q++) {
            float4 s4 = *(const float4*)&g_S[base + q*4];
            h[q*4+0] = h[q*4+0]*dec + s4.x;
            h[q*4+1] = h[q*4+1]*dec + s4.y;
            h[q*4+2] = h[q*4+2]*dec + s4.z;
            h[q*4+3] = h[q*4+3]*dec + s4.w;
        }
    }
}

// ---------------- k_Yc: y_raw = M.X + E*(C.H0) per (chunk, p-quarter) --------
#define CTPAD 132
#define KYC_SMEM ((QC*QC + QC*128 + DSTATE*CTPAD + DSTATE*128)*4)  // 197632 B
__global__ __launch_bounds__(256, 1) void k_Yc() {
    extern __shared__ float sm[];
    float* Mt = sm;                          // [128][128]
    float* Xs = Mt + QC*QC;                  // [128][128]
    float* Ct = Xs + QC*128;                 // [64][132]
    float* Hs = Ct + DSTATE*CTPAD;           // [64][128]
    int bc = blockIdx.x;
    int pq = blockIdx.y;
    int tid = threadIdx.x;
    int rowbase = (bc >> 4)*SEQL + (bc & 15)*QC;
    int p0 = pq*128;

    // stage M (16 f4/thread), X (16 f4), H (8 f4), Ct (32 scalars)
    const float4* Msrc = (const float4*)(g_M + (size_t)bc*QC*QC);
    #pragma unroll
    for (int j = 0; j < 16; j++) {
        int e = j*256 + tid;
        ((float4*)Mt)[e] = Msrc[e];
    }
    #pragma unroll
    for (int j = 0; j < 16; j++) {
        int e = j*256 + tid; int s = e >> 5, p4 = e & 31;
        ((float4*)Xs)[e] = *(const float4*)&g_xbc[(size_t)(rowbase+s)*CONVDIM + p0 + p4*4];
    }
    #pragma unroll
    for (int j = 0; j < 8; j++) {
        int e = j*256 + tid; int n = e >> 5, p4 = e & 31;
        *(float4*)&Hs[n*128 + p4*4] = *(const float4*)&g_H[((size_t)bc*DSTATE + n)*DINNER + p0 + p4*4];
    }
    #pragma unroll
    for (int j = 0; j < 32; j++) {
        int e = j*256 + tid; int ii = e >> 6, n = e & 63;
        Ct[n*CTPAD + ii] = g_xbc[(size_t)(rowbase+ii)*CONVDIM + DINNER + DSTATE + n];
    }
    __syncthreads();

    int w = tid >> 5, lane = tid & 31;
    int r0 = w*16 + (lane >> 4)*8;
    int c0 = (lane & 15)*8;
    float acc[8][8];
    #pragma unroll
    for (int r = 0; r < 8; r++)
        #pragma unroll
        for (int cc = 0; cc < 8; cc++) acc[r][cc] = 0.f;

    int kmax = w*16 + 16;      // causal: rows in this warp need k <= w*16+15
    for (int k = 0; k < kmax; k++) {
        float4 m0 = *(const float4*)&Mt[k*128 + r0];
        float4 m1 = *(const float4*)&Mt[k*128 + r0 + 4];
        float4 x0 = *(const float4*)&Xs[k*128 + c0];
        float4 x1 = *(const float4*)&Xs[k*128 + c0 + 4];
        float mm[8] = {m0.x,m0.y,m0.z,m0.w,m1.x,m1.y,m1.z,m1.w};
        float xx[8] = {x0.x,x0.y,x0.z,x0.w,x1.x,x1.y,x1.z,x1.w};
        #pragma unroll
        for (int r = 0; r < 8; r++)
            #pragma unroll
            for (int cc = 0; cc < 8; cc++) acc[r][cc] += mm[r]*xx[cc];
    }

    if (bc & 15) {   // inter-chunk (chunk 0 has H0 = 0)
        float Er[8];
        #pragma unroll
        for (int r = 0; r < 8; r++) Er[r] = expf(g_cum[rowbase + r0 + r]);
        for (int n = 0; n < DSTATE; n++) {
            float4 cv0 = *(const float4*)&Ct[n*CTPAD + r0];
            float4 cv1 = *(const float4*)&Ct[n*CTPAD + r0 + 4];
            float4 h0 = *(const float4*)&Hs[n*128 + c0];
            float4 h1 = *(const float4*)&Hs[n*128 + c0 + 4];
            float mm[8] = {cv0.x*Er[0],cv0.y*Er[1],cv0.z*Er[2],cv0.w*Er[3],
                           cv1.x*Er[4],cv1.y*Er[5],cv1.z*Er[6],cv1.w*Er[7]};
            float hh[8] = {h0.x,h0.y,h0.z,h0.w,h1.x,h1.y,h1.z,h1.w};
            #pragma unroll
            for (int r = 0; r < 8; r++)
                #pragma unroll
                for (int cc = 0; cc < 8; cc++) acc[r][cc] += mm[r]*hh[cc];
        }
    }

    #pragma unroll
    for (int r = 0; r < 8; r++) {
        float* dst = g_y + (size_t)(rowbase + r0 + r)*DINNER + p0 + c0;
        *(float4*)dst       = make_float4(acc[r][0], acc[r][1], acc[r][2], acc[r][3]);
        *(float4*)(dst + 4) = make_float4(acc[r][4], acc[r][5], acc[r][6], acc[r][7]);
    }
}

// ---------------- k_gate: y = rmsnorm(y_raw * silu(z)) * ngw ----------------
__global__ __launch_bounds__(128) void k_gate(const float* __restrict__ ngw) {
    int row = blockIdx.x, tid = threadIdx.x;
    float4 y = *(const float4*)&g_y[(size_t)row*DINNER + tid*4];
    float4 z = *(const float4*)&g_zx[(size_t)row*ZSTRIDE + tid*4];
    float g0 = y.x * (z.x / (1.f + expf(-z.x)));
    float g1 = y.y * (z.y / (1.f + expf(-z.y)));
    float g2 = y.z * (z.z / (1.f + expf(-z.z)));
    float g3 = y.w * (z.w / (1.f + expf(-z.w)));
    float s = g0*g0 + g1*g1 + g2*g2 + g3*g3;
    #pragma unroll
    for (int o = 16; o > 0; o >>= 1) s += __shfl_xor_sync(0xffffffffu, s, o);
    __shared__ float wred[4];
    if ((tid & 31) == 0) wred[tid >> 5] = s;
    __syncthreads();
    float tot = wred[0] + wred[1] + wred[2] + wred[3];
    float rs = rsqrtf(tot*(1.f/DINNER) + 1e-5f);
    float4 gw = *(const float4*)&ngw[tid*4];
    *(float4*)&g_y[(size_t)row*DINNER + tid*4] =
        make_float4(g0*rs*gw.x, g1*rs*gw.y, g2*rs*gw.z, g3*rs*gw.w);
}

// ---------------- final ----------------
__global__ __launch_bounds__(256) void k_final(const float* __restrict__ nfw,
                                               const float* __restrict__ embed,
                                               float* __restrict__ out) {
    int b = blockIdx.x, t = threadIdx.x;
    int row = b*SEQL + SEQL - 1;
    float v = g_res[row*DMODEL + t] + g_hid[row*DMODEL + t];
    __shared__ float fin[256];
    __shared__ float sred[256];
    sred[t] = v*v; __syncthreads();
    #pragma unroll
    for (int s = 128; s > 0; s >>= 1) {
        if (t < s) sred[t] += sred[t+s];
        __syncthreads();
    }
    float rs = rsqrtf(sred[0]*(1.f/DMODEL) + 1e-5f);
    fin[t] = v*rs*nfw[t]; __syncthreads();
    if (t < 100) {
        float accv = 0.f;
        #pragma unroll 8
        for (int d = 0; d < DMODEL; d++) accv += fin[d]*embed[t*DMODEL + d];
        out[b*100 + t] = accv;
    }
}

// ---------------- launch ----------------
extern "C" void kernel_launch(void* const* d_in, const int* in_sizes, int n_in,
                              void* d_out, int out_size) {
    const int*   ids   = (const int*)  d_in[0];
    const float* embed = (const float*)d_in[1];
    const float* ipw   = (const float*)d_in[2];
    const float* cw    = (const float*)d_in[3];
    const float* cb    = (const float*)d_in[4];
    const float* dtb   = (const float*)d_in[5];
    const float* alog  = (const float*)d_in[6];
    const float* dpar  = (const float*)d_in[7];
    const float* ngw   = (const float*)d_in[8];
    const float* opw   = (const float*)d_in[9];
    const float* bnw   = (const float*)d_in[10];
    const float* nfw   = (const float*)d_in[11];
    float* out = (float*)d_out;

    cudaFuncSetAttribute(gemm_bf3, cudaFuncAttributeMaxDynamicSharedMemorySize, GEMM_SMEM);
    cudaFuncSetAttribute(k_M,  cudaFuncAttributeMaxDynamicSharedMemorySize, KM_SMEM);
    cudaFuncSetAttribute(k_Yc, cudaFuncAttributeMaxDynamicSharedMemorySize, KYC_SMEM);

    k_embed<<<ROWS, 256>>>(ids, embed);
    for (int L = 0; L < 4; L++) {
        k_resnorm<<<ROWS, 256>>>(bnw + L*DMODEL, L > 0);
        if (L == 0) k_probe<<<1, 32>>>();    // shifts gemm0 into the ncu capture slot
        gemm_bf3<<<dim3(10, ROWS/128), 256, GEMM_SMEM>>>(0, ipw + (size_t)L*DINPROJ*DMODEL,
                                                         DMODEL, DINPROJ, ZSTRIDE);
        k_conv<<<((ROWS/4)*CONVDIM + 255)/256, 256>>>(cw + L*CONVDIM*4, cb + L*CONVDIM);
        k_M<<<BATCH*NCH, 256, KM_SMEM>>>(dtb + L, alog + L, dpar + L);
        k_S<<<dim3(BATCH*NCH, 4), 256>>>();
        k_H<<<dim3(BATCH, 8), 256>>>();
        k_Yc<<<dim3(BATCH*NCH, 4), 256, KYC_SMEM>>>();
        k_gate<<<ROWS, 128>>>(ngw + L*DINNER);
        gemm_bf3<<<dim3(2, ROWS/128), 256, GEMM_SMEM>>>(1, opw + (size_t)L*DMODEL*DINNER,
                                                        DINNER, DMODEL, DMODEL);
    }
    k_final<<<BATCH, 256>>>(nfw, embed, out);
}

// round 14
// speedup vs baseline: 2.2770x; 1.1625x over previous
#include <cuda_runtime.h>
#include <cuda_bf16.h>
#include <math.h>
#include <stdint.h>

#define BATCH 8
#define SEQL 2048
#define ROWS (BATCH*SEQL)     // 16384
#define DMODEL 256
#define DINNER 512
#define DSTATE 64
#define CONVDIM 640
#define DINPROJ 1153
#define NPADI 1280
#define ZSTRIDE 1280
#define QC 128
#define NCH (SEQL/QC)         // 16

// ---------------- scratch ----------------
__device__ float g_res[ROWS*DMODEL];
__device__ float g_hid[ROWS*DMODEL];
__device__ float g_zx [(size_t)ROWS*ZSTRIDE];
__device__ float g_xbc[ROWS*CONVDIM];
__device__ float g_y  [ROWS*DINNER];
__device__ float g_dt [ROWS];
__device__ float g_cum[ROWS];
__device__ float g_S[BATCH*NCH*DSTATE*DINNER];
__device__ float g_H[BATCH*NCH*DSTATE*DINNER];
__device__ float g_M[(size_t)BATCH*NCH*QC*QC];

// bf16 hi/lo operands
__device__ __nv_bfloat16 g_ah[ROWS*DMODEL], g_al[ROWS*DMODEL];
__device__ __nv_bfloat16 g_yh[ROWS*DINNER], g_yl[ROWS*DINNER];
__device__ __nv_bfloat16 g_wih[4*NPADI*DMODEL], g_wil[4*NPADI*DMODEL];
__device__ __nv_bfloat16 g_woh[4*DMODEL*DINNER], g_wol[4*DMODEL*DINNER];

__device__ __forceinline__ uint32_t smem_to_u32(const void* p) {
    uint32_t a;
    asm("{ .reg .u64 t; cvta.to.shared.u64 t, %1; cvt.u32.u64 %0, t; }" : "=r"(a) : "l"(p));
    return a;
}

// ---------------- one-shot weight conversion (fp32 -> bf16 hi/lo) ------------
__global__ __launch_bounds__(256) void k_wcvt(const float* __restrict__ ipw,
                                              const float* __restrict__ opw) {
    int idx = blockIdx.x*256 + threadIdx.x;
    const int NI = 4*NPADI*DMODEL;
    const int NO = 4*DMODEL*DINNER;
    if (idx < NI) {
        int l = idx / (NPADI*DMODEL);
        int r = (idx / DMODEL) % NPADI;
        int c = idx % DMODEL;
        float v = (r < DINPROJ) ? ipw[((size_t)l*DINPROJ + r)*DMODEL + c] : 0.f;
        __nv_bfloat16 h = __float2bfloat16(v);
        g_wih[idx] = h;
        g_wil[idx] = __float2bfloat16(v - __bfloat162float(h));
    } else if (idx - NI < NO) {
        int j = idx - NI;
        float v = opw[j];
        __nv_bfloat16 h = __float2bfloat16(v);
        g_woh[j] = h;
        g_wol[j] = __float2bfloat16(v - __bfloat162float(h));
    }
}

// ---------------- embed gather ----------------
__global__ __launch_bounds__(256) void k_embed(const int* __restrict__ ids,
                                               const float* __restrict__ embed) {
    int row = blockIdx.x, t = threadIdx.x;
    g_res[row*DMODEL + t] = embed[ids[row]*DMODEL + t];
}

// ---------------- residual add + rmsnorm -> bf16 hi/lo A --------------------
__global__ __launch_bounds__(256) void k_resnorm(const float* __restrict__ w, int add) {
    int row = blockIdx.x, t = threadIdx.x;
    float v = g_res[row*DMODEL + t];
    if (add) { v += g_hid[row*DMODEL + t]; g_res[row*DMODEL + t] = v; }
    float s = v*v;
    #pragma unroll
    for (int o = 16; o > 0; o >>= 1) s += __shfl_xor_sync(0xffffffffu, s, o);
    __shared__ float wred[8];
    if ((t & 31) == 0) wred[t >> 5] = s;
    __syncthreads();
    float tot = wred[0]+wred[1]+wred[2]+wred[3]+wred[4]+wred[5]+wred[6]+wred[7];
    float rs = rsqrtf(tot*(1.f/DMODEL) + 1e-5f);
    float o = v * rs * w[t];
    __nv_bfloat16 h = __float2bfloat16(o);
    g_ah[row*DMODEL + t] = h;
    g_al[row*DMODEL + t] = __float2bfloat16(o - __bfloat162float(h));
}

// =================== bf16 mma GEMM, cp.async double-buffered ===================
#define KT 32
#define ASTRIDE 40
#define ARR_BYTES (128*ASTRIDE*2)        // 10240
#define STAGE_BYTES (4*ARR_BYTES)        // 40KB
#define GEMM_SMEM (2*STAGE_BYTES)        // 80KB

#define LDM4(r, addr) \
    asm volatile("ldmatrix.sync.aligned.m8n8.x4.shared.b16 {%0,%1,%2,%3}, [%4];" \
        : "=r"((r)[0]), "=r"((r)[1]), "=r"((r)[2]), "=r"((r)[3]) : "r"(addr))

#define MMA16816(c, a, b0, b1) \
    asm volatile("mma.sync.aligned.m16n8k16.row.col.f32.bf16.bf16.f32 " \
        "{%0,%1,%2,%3}, {%4,%5,%6,%7}, {%8,%9}, {%0,%1,%2,%3};" \
        : "+f"((c)[0]), "+f"((c)[1]), "+f"((c)[2]), "+f"((c)[3]) \
        : "r"((a)[0]), "r"((a)[1]), "r"((a)[2]), "r"((a)[3]), "r"(b0), "r"(b1))

#define CPA16(s, g) \
    asm volatile("cp.async.cg.shared.global [%0], [%1], 16;" :: "r"(s), "l"(g))
#define CPA_COMMIT() asm volatile("cp.async.commit_group;" ::: "memory")
#define CPA_WAIT(n)  asm volatile("cp.async.wait_group %0;" :: "n"(n) : "memory")

__device__ __forceinline__ void gemm_load_stage(
    uint32_t base, const __nv_bfloat16* Ah, const __nv_bfloat16* Al,
    const __nv_bfloat16* Bh, const __nv_bfloat16* Bl,
    int m0, int n0, int k0, int K, int tid)
{
    #pragma unroll
    for (int j = 0; j < 8; j++) {
        int e = j*256 + tid;            // 0..2047
        int arr = e >> 9;
        int idx = e & 511;
        int row = idx >> 2, ch = idx & 3;
        const __nv_bfloat16* src;
        if (arr == 0)      src = Ah + (size_t)(m0+row)*K;
        else if (arr == 1) src = Al + (size_t)(m0+row)*K;
        else if (arr == 2) src = Bh + (size_t)(n0+row)*K;
        else               src = Bl + (size_t)(n0+row)*K;
        uint32_t saddr = base + (uint32_t)arr*ARR_BYTES + (uint32_t)(row*80 + ch*16);
        CPA16(saddr, src + k0 + ch*8);
    }
}

__global__ __launch_bounds__(256, 2) void gemm_bf3(int which, int woff, int K, int ldc) {
    extern __shared__ char smem[];
    const __nv_bfloat16 *Ah, *Al, *Bh, *Bl; float* C;
    if (which == 0) { Ah = g_ah; Al = g_al; Bh = g_wih + woff; Bl = g_wil + woff; C = g_zx; }
    else            { Ah = g_yh; Al = g_yl; Bh = g_woh + woff; Bl = g_wol + woff; C = g_hid; }

    uint32_t sb = smem_to_u32(smem);
    int tid = threadIdx.x;
    int wid = tid >> 5, lane = tid & 31;
    int m0 = blockIdx.y * 128;
    int n0 = blockIdx.x * 128;
    int wm = wid >> 2, wn = wid & 3;
    int nkt = K / KT;

    float c[4][4][4];
    #pragma unroll
    for (int i = 0; i < 4; i++)
        #pragma unroll
        for (int j = 0; j < 4; j++)
            #pragma unroll
            for (int q = 0; q < 4; q++) c[i][j][q] = 0.f;

    uint32_t a_off = (uint32_t)((lane & 15)*(ASTRIDE*2) + (lane >> 4)*16);
    uint32_t b_off = (uint32_t)(((lane & 7) + ((lane >> 4) << 3))*(ASTRIDE*2) + ((lane >> 3) & 1)*16);

    // prologue: stage 0
    gemm_load_stage(sb, Ah, Al, Bh, Bl, m0, n0, 0, K, tid);
    CPA_COMMIT();

    for (int kt = 0; kt < nkt; kt++) {
        int st = kt & 1;
        if (kt + 1 < nkt) {
            gemm_load_stage(sb + ((kt+1)&1)*STAGE_BYTES, Ah, Al, Bh, Bl,
                            m0, n0, (kt+1)*KT, K, tid);
            CPA_COMMIT();
            CPA_WAIT(1);
        } else {
            CPA_WAIT(0);
        }
        __syncthreads();

        uint32_t base = sb + st*STAGE_BYTES;
        uint32_t ahi = base, alo = base + ARR_BYTES;
        uint32_t bhi = base + 2*ARR_BYTES, blo = base + 3*ARR_BYTES;

        #pragma unroll
        for (int h = 0; h < 2; h++) {
            uint32_t kh = h*32;
            uint32_t Bhf[2][4], Blf[2][4];
            #pragma unroll
            for (int g = 0; g < 2; g++) {
                uint32_t rb = (uint32_t)((wn*32 + g*16)*(ASTRIDE*2)) + kh + b_off;
                LDM4(Bhf[g], bhi + rb);
                LDM4(Blf[g], blo + rb);
            }
            #pragma unroll
            for (int mf = 0; mf < 4; mf++) {
                uint32_t Ahf[4], Alf[4];
                uint32_t rb = (uint32_t)((wm*64 + mf*16)*(ASTRIDE*2)) + kh + a_off;
                LDM4(Ahf, ahi + rb);
                LDM4(Alf, alo + rb);
                #pragma unroll
                for (int nf = 0; nf < 4; nf++) {
                    int g = nf >> 1, o = (nf & 1)*2;
                    MMA16816(c[mf][nf], Ahf, Bhf[g][o], Bhf[g][o+1]);
                    MMA16816(c[mf][nf], Alf, Bhf[g][o], Bhf[g][o+1]);
                    MMA16816(c[mf][nf], Ahf, Blf[g][o], Blf[g][o+1]);
                }
            }
        }
        __syncthreads();
    }

    #pragma unroll
    for (int mf = 0; mf < 4; mf++) {
        int r0 = m0 + wm*64 + mf*16 + (lane >> 2);
        #pragma unroll
        for (int nf = 0; nf < 4; nf++) {
            int col = n0 + wn*32 + nf*8 + (lane & 3)*2;
            *(float2*)&C[(size_t)r0*ldc + col]     = make_float2(c[mf][nf][0], c[mf][nf][1]);
            *(float2*)&C[(size_t)(r0+8)*ldc + col] = make_float2(c[mf][nf][2], c[mf][nf][3]);
        }
    }
}

// ---------------- conv: 4 timesteps per thread, rolling window ----------------
__global__ __launch_bounds__(256) void k_conv(const float* __restrict__ cw,
                                              const float* __restrict__ cb) {
    int idx = blockIdx.x*256 + threadIdx.x;
    if (idx >= (ROWS/4)*CONVDIM) return;
    int c  = idx % CONVDIM;
    int tg = idx / CONVDIM;
    int row0 = tg*4;
    int t0 = row0 & (SEQL-1);
    float w0 = cw[c*4+0], w1 = cw[c*4+1], w2 = cw[c*4+2], w3 = cw[c*4+3];
    float bias = cb[c];
    const float* base = g_zx + (size_t)row0*ZSTRIDE + DINNER + c;
    float v[7];
    #pragma unroll
    for (int j = 0; j < 3; j++)
        v[j] = (t0 + j >= 3) ? base[(j-3)*ZSTRIDE] : 0.f;
    #pragma unroll
    for (int j = 3; j < 7; j++)
        v[j] = base[(j-3)*ZSTRIDE];
    #pragma unroll
    for (int k = 0; k < 4; k++) {
        float acc = bias + v[k]*w0 + v[k+1]*w1 + v[k+2]*w2 + v[k+3]*w3;
        g_xbc[(size_t)(row0+k)*CONVDIM + c] = acc / (1.f + expf(-acc));
    }
}

// ---------------- k_M: dt softplus + cumsum + chunk M matrix (transposed) ----
#define MPAD 65
#define KM_SMEM ((2*QC*MPAD + 2*QC)*4)
__global__ __launch_bounds__(256) void k_M(const float* __restrict__ dtb,
                                           const float* __restrict__ alog,
                                           const float* __restrict__ dparam) {
    extern __shared__ float sm[];
    float* Bs   = sm;
    float* Cs   = Bs + QC*MPAD;
    float* scum = Cs + QC*MPAD;
    float* sdt  = scum + QC;
    int bc = blockIdx.x;
    int tid = threadIdx.x;
    int rowbase = (bc >> 4)*SEQL + (bc & 15)*QC;

    if (tid < QC) {
        float raw = g_zx[(size_t)(rowbase+tid)*ZSTRIDE + 1152] + dtb[0];
        sdt[tid] = (raw > 20.f) ? raw : log1pf(expf(raw));
    }
    #pragma unroll
    for (int j = 0; j < 32; j++) {
        int e = j*256 + tid; int ii = e >> 6, n = e & 63;
        const float* src = g_xbc + (size_t)(rowbase+ii)*CONVDIM + DINNER;
        Bs[ii*MPAD + n] = src[n];
        Cs[ii*MPAD + n] = src[DSTATE + n];
    }
    __syncthreads();
    if (tid == 0) {
        float A = -expf(alog[0]);
        float cacc = 0.f;
        for (int j = 0; j < QC; j++) { cacc += sdt[j]*A; scum[j] = cacc; }
    }
    __syncthreads();
    if (tid < QC) { g_dt[rowbase+tid] = sdt[tid]; g_cum[rowbase+tid] = scum[tid]; }

    int i  = tid >> 1;
    int s0 = (tid & 1)*64;
    float dpv = dparam[0];
    float ci  = scum[i];
    float* Mo = g_M + ((size_t)bc*QC)*QC;
    for (int sj = 0; sj < 64; sj++) {
        int s = s0 + sj;
        float m = 0.f;
        if (s <= i) {
            float dot = 0.f;
            #pragma unroll 16
            for (int n = 0; n < 64; n++) dot += Cs[i*MPAD+n]*Bs[s*MPAD+n];
            m = expf(ci - scum[s]) * sdt[s] * dot;
            if (s == i) m += dpv;
        }
        Mo[(size_t)s*QC + i] = m;
    }
}

// ---------------- chunk state S ----------------
__global__ __launch_bounds__(256) void k_S() {
    int bc = blockIdx.x;
    int pt = blockIdx.y;
    int rowbase = (bc >> 4)*SEQL + (bc & 15)*QC;
    float cl = g_cum[rowbase + QC - 1];
    __shared__ __align__(16) float Bw[16][64];
    __shared__ __align__(16) float Xs[16][128];
    int tid = threadIdx.x;
    int nt = tid >> 4, ptg = tid & 15;
    float acc[4][8];
    #pragma unroll
    for (int a = 0; a < 4; a++)
        #pragma unroll
        for (int b = 0; b < 8; b++) acc[a][b] = 0.f;

    int eb = tid*4; int bii = eb >> 6, bn0 = eb & 63;
    int ex = tid*8; int xii = ex >> 7, xp0 = ex & 127;

    for (int i0 = 0; i0 < QC; i0 += 16) {
        int rb = rowbase + i0 + bii;
        float coef = expf(cl - g_cum[rb]) * g_dt[rb];
        #pragma unroll
        for (int j = 0; j < 4; j++)
            Bw[bii][bn0+j] = coef * g_xbc[(size_t)rb*CONVDIM + DINNER + bn0 + j];
        int rx = rowbase + i0 + xii;
        #pragma unroll
        for (int j = 0; j < 8; j++)
            Xs[xii][xp0+j] = g_xbc[(size_t)rx*CONVDIM + pt*128 + xp0 + j];
        __syncthreads();
        #pragma unroll
        for (int kk = 0; kk < 16; kk++) {
            float4 av = *(const float4*)&Bw[kk][nt*4];
            float a[4] = {av.x, av.y, av.z, av.w};
            #pragma unroll
            for (int q = 0; q < 2; q++) {
                float4 xv = *(const float4*)&Xs[kk][ptg*4 + q*64];
                #pragma unroll
                for (int nn = 0; nn < 4; nn++) {
                    acc[nn][q*4+0] += a[nn]*xv.x;
                    acc[nn][q*4+1] += a[nn]*xv.y;
                    acc[nn][q*4+2] += a[nn]*xv.z;
                    acc[nn][q*4+3] += a[nn]*xv.w;
                }
            }
        }
        __syncthreads();
    }
    #pragma unroll
    for (int nn = 0; nn < 4; nn++) {
        int n = nt*4 + nn;
        #pragma unroll
        for (int q = 0; q < 2; q++) {
            float4 st = make_float4(acc[nn][q*4], acc[nn][q*4+1], acc[nn][q*4+2], acc[nn][q*4+3]);
            *(float4*)&g_S[((size_t)bc*DSTATE + n)*DINNER + pt*128 + ptg*4 + q*64] = st;
        }
    }
}

// ---------------- chunk-boundary recurrence ----------------
__global__ __launch_bounds__(256) void k_H() {
    int b = blockIdx.x, ps = blockIdx.y;
    int tid = threadIdx.x;
    int n = tid >> 2;
    int p0 = ps*64 + (tid & 3)*16;
    float h[16];
    #pragma unroll
    for (int q = 0; q < 16; q++) h[q] = 0.f;
    for (int c = 0; c < NCH; c++) {
        size_t base = ((size_t)(b*NCH + c)*DSTATE + n)*DINNER + p0;
        #pragma unroll
        for (int q = 0; q < 4; q++)
            *(float4*)&g_H[base + q*4] = make_float4(h[q*4], h[q*4+1], h[q*4+2], h[q*4+3]);
        float dec = expf(g_cum[b*SEQL + c*QC + QC - 1]);
        #pragma unroll
        for (int q = 0; q < 4; q++) {
            float4 s4 = *(const float4*)&g_S[base + q*4];
            h[q*4+0] = h[q*4+0]*dec + s4.x;
            h[q*4+1] = h[q*4+1]*dec + s4.y;
            h[q*4+2] = h[q*4+2]*dec + s4.z;
            h[q*4+3] = h[q*4+3]*dec + s4.w;
        }
    }
}

// ---------------- k_Yc: y_raw = M.X + E*(C.H0) per (chunk, p-quarter) --------
#define CTPAD 132
#define KYC_SMEM ((QC*QC + QC*128 + DSTATE*CTPAD + DSTATE*128)*4)
__global__ __launch_bounds__(256, 1) void k_Yc() {
    extern __shared__ float sm[];
    float* Mt = sm;
    float* Xs = Mt + QC*QC;
    float* Ct = Xs + QC*128;
    float* Hs = Ct + DSTATE*CTPAD;
    int bc = blockIdx.x;
    int pq = blockIdx.y;
    int tid = threadIdx.x;
    int rowbase = (bc >> 4)*SEQL + (bc & 15)*QC;
    int p0 = pq*128;

    const float4* Msrc = (const float4*)(g_M + (size_t)bc*QC*QC);
    #pragma unroll
    for (int j = 0; j < 16; j++) {
        int e = j*256 + tid;
        ((float4*)Mt)[e] = Msrc[e];
    }
    #pragma unroll
    for (int j = 0; j < 16; j++) {
        int e = j*256 + tid; int s = e >> 5, p4 = e & 31;
        ((float4*)Xs)[e] = *(const float4*)&g_xbc[(size_t)(rowbase+s)*CONVDIM + p0 + p4*4];
    }
    #pragma unroll
    for (int j = 0; j < 8; j++) {
        int e = j*256 + tid; int n = e >> 5, p4 = e & 31;
        *(float4*)&Hs[n*128 + p4*4] = *(const float4*)&g_H[((size_t)bc*DSTATE + n)*DINNER + p0 + p4*4];
    }
    #pragma unroll
    for (int j = 0; j < 32; j++) {
        int e = j*256 + tid; int ii = e >> 6, n = e & 63;
        Ct[n*CTPAD + ii] = g_xbc[(size_t)(rowbase+ii)*CONVDIM + DINNER + DSTATE + n];
    }
    __syncthreads();

    int w = tid >> 5, lane = tid & 31;
    int r0 = w*16 + (lane >> 4)*8;
    int c0 = (lane & 15)*8;
    float acc[8][8];
    #pragma unroll
    for (int r = 0; r < 8; r++)
        #pragma unroll
        for (int cc = 0; cc < 8; cc++) acc[r][cc] = 0.f;

    int kmax = w*16 + 16;
    for (int k = 0; k < kmax; k++) {
        float4 m0 = *(const float4*)&Mt[k*128 + r0];
        float4 m1 = *(const float4*)&Mt[k*128 + r0 + 4];
        float4 x0 = *(const float4*)&Xs[k*128 + c0];
        float4 x1 = *(const float4*)&Xs[k*128 + c0 + 4];
        float mm[8] = {m0.x,m0.y,m0.z,m0.w,m1.x,m1.y,m1.z,m1.w};
        float xx[8] = {x0.x,x0.y,x0.z,x0.w,x1.x,x1.y,x1.z,x1.w};
        #pragma unroll
        for (int r = 0; r < 8; r++)
            #pragma unroll
            for (int cc = 0; cc < 8; cc++) acc[r][cc] += mm[r]*xx[cc];
    }

    if (bc & 15) {
        float Er[8];
        #pragma unroll
        for (int r = 0; r < 8; r++) Er[r] = expf(g_cum[rowbase + r0 + r]);
        for (int n = 0; n < DSTATE; n++) {
            float4 cv0 = *(const float4*)&Ct[n*CTPAD + r0];
            float4 cv1 = *(const float4*)&Ct[n*CTPAD + r0 + 4];
            float4 h0 = *(const float4*)&Hs[n*128 + c0];
            float4 h1 = *(const float4*)&Hs[n*128 + c0 + 4];
            float mm[8] = {cv0.x*Er[0],cv0.y*Er[1],cv0.z*Er[2],cv0.w*Er[3],
                           cv1.x*Er[4],cv1.y*Er[5],cv1.z*Er[6],cv1.w*Er[7]};
            float hh[8] = {h0.x,h0.y,h0.z,h0.w,h1.x,h1.y,h1.z,h1.w};
            #pragma unroll
            for (int r = 0; r < 8; r++)
                #pragma unroll
                for (int cc = 0; cc < 8; cc++) acc[r][cc] += mm[r]*hh[cc];
        }
    }

    #pragma unroll
    for (int r = 0; r < 8; r++) {
        float* dst = g_y + (size_t)(rowbase + r0 + r)*DINNER + p0 + c0;
        *(float4*)dst       = make_float4(acc[r][0], acc[r][1], acc[r][2], acc[r][3]);
        *(float4*)(dst + 4) = make_float4(acc[r][4], acc[r][5], acc[r][6], acc[r][7]);
    }
}

// ---------------- k_gate: y = rmsnorm(y_raw * silu(z)) * ngw -> bf16 hi/lo ---
__global__ __launch_bounds__(128) void k_gate(const float* __restrict__ ngw) {
    int row = blockIdx.x, tid = threadIdx.x;
    float4 y = *(const float4*)&g_y[(size_t)row*DINNER + tid*4];
    float4 z = *(const float4*)&g_zx[(size_t)row*ZSTRIDE + tid*4];
    float g0 = y.x * (z.x / (1.f + expf(-z.x)));
    float g1 = y.y * (z.y / (1.f + expf(-z.y)));
    float g2 = y.z * (z.z / (1.f + expf(-z.z)));
    float g3 = y.w * (z.w / (1.f + expf(-z.w)));
    float s = g0*g0 + g1*g1 + g2*g2 + g3*g3;
    #pragma unroll
    for (int o = 16; o > 0; o >>= 1) s += __shfl_xor_sync(0xffffffffu, s, o);
    __shared__ float wred[4];
    if ((tid & 31) == 0) wred[tid >> 5] = s;
    __syncthreads();
    float tot = wred[0] + wred[1] + wred[2] + wred[3];
    float rs = rsqrtf(tot*(1.f/DINNER) + 1e-5f);
    float4 gw = *(const float4*)&ngw[tid*4];
    float o0 = g0*rs*gw.x, o1 = g1*rs*gw.y, o2 = g2*rs*gw.z, o3 = g3*rs*gw.w;
    size_t base = (size_t)row*DINNER + tid*4;
    __nv_bfloat16 h0 = __float2bfloat16(o0), h1 = __float2bfloat16(o1);
    __nv_bfloat16 h2 = __float2bfloat16(o2), h3 = __float2bfloat16(o3);
    *(uint2*)&g_yh[base] = *(uint2*)&(__nv_bfloat162[2]){
        {h0, h1}, {h2, h3}};
    __nv_bfloat16 l0 = __float2bfloat16(o0 - __bfloat162float(h0));
    __nv_bfloat16 l1 = __float2bfloat16(o1 - __bfloat162float(h1));
    __nv_bfloat16 l2 = __float2bfloat16(o2 - __bfloat162float(h2));
    __nv_bfloat16 l3 = __float2bfloat16(o3 - __bfloat162float(h3));
    __nv_bfloat162 lp0 = {l0, l1}, lp1 = {l2, l3};
    uint2 lv = make_uint2(*(uint32_t*)&lp0, *(uint32_t*)&lp1);
    *(uint2*)&g_yl[base] = lv;
}

// ---------------- final ----------------
__global__ __launch_bounds__(256) void k_final(const float* __restrict__ nfw,
                                               const float* __restrict__ embed,
                                               float* __restrict__ out) {
    int b = blockIdx.x, t = threadIdx.x;
    int row = b*SEQL + SEQL - 1;
    float v = g_res[row*DMODEL + t] + g_hid[row*DMODEL + t];
    __shared__ float fin[256];
    __shared__ float sred[256];
    sred[t] = v*v; __syncthreads();
    #pragma unroll
    for (int s = 128; s > 0; s >>= 1) {
        if (t < s) sred[t] += sred[t+s];
        __syncthreads();
    }
    float rs = rsqrtf(sred[0]*(1.f/DMODEL) + 1e-5f);
    fin[t] = v*rs*nfw[t]; __syncthreads();
    if (t < 100) {
        float accv = 0.f;
        #pragma unroll 8
        for (int d = 0; d < DMODEL; d++) accv += fin[d]*embed[t*DMODEL + d];
        out[b*100 + t] = accv;
    }
}

// ---------------- launch ----------------
extern "C" void kernel_launch(void* const* d_in, const int* in_sizes, int n_in,
                              void* d_out, int out_size) {
    const int*   ids   = (const int*)  d_in[0];
    const float* embed = (const float*)d_in[1];
    const float* ipw   = (const float*)d_in[2];
    const float* cw    = (const float*)d_in[3];
    const float* cb    = (const float*)d_in[4];
    const float* dtb   = (const float*)d_in[5];
    const float* alog  = (const float*)d_in[6];
    const float* dpar  = (const float*)d_in[7];
    const float* ngw   = (const float*)d_in[8];
    const float* opw   = (const float*)d_in[9];
    const float* bnw   = (const float*)d_in[10];
    const float* nfw   = (const float*)d_in[11];
    float* out = (float*)d_out;

    cudaFuncSetAttribute(gemm_bf3, cudaFuncAttributeMaxDynamicSharedMemorySize, GEMM_SMEM);
    cudaFuncSetAttribute(k_M,  cudaFuncAttributeMaxDynamicSharedMemorySize, KM_SMEM);
    cudaFuncSetAttribute(k_Yc, cudaFuncAttributeMaxDynamicSharedMemorySize, KYC_SMEM);

    int wtot = 4*NPADI*DMODEL + 4*DMODEL*DINNER;
    k_wcvt<<<(wtot + 255)/256, 256>>>(ipw, opw);
    k_embed<<<ROWS, 256>>>(ids, embed);
    for (int L = 0; L < 4; L++) {
        k_resnorm<<<ROWS, 256>>>(bnw + L*DMODEL, L > 0);
        gemm_bf3<<<dim3(10, ROWS/128), 256, GEMM_SMEM>>>(0, L*NPADI*DMODEL, DMODEL, ZSTRIDE);
        k_conv<<<((ROWS/4)*CONVDIM + 255)/256, 256>>>(cw + L*CONVDIM*4, cb + L*CONVDIM);
        k_M<<<BATCH*NCH, 256, KM_SMEM>>>(dtb + L, alog + L, dpar + L);
        k_S<<<dim3(BATCH*NCH, 4), 256>>>();
        k_H<<<dim3(BATCH, 8), 256>>>();
        k_Yc<<<dim3(BATCH*NCH, 4), 256, KYC_SMEM>>>();
        k_gate<<<ROWS, 128>>>(ngw + L*DINNER);
        gemm_bf3<<<dim3(2, ROWS/128), 256, GEMM_SMEM>>>(1, L*DMODEL*DINNER, DINNER, DMODEL);
    }
    k_final<<<BATCH, 256>>>(nfw, embed, out);
}

// round 15
// speedup vs baseline: 2.3258x; 1.0214x over previous
#include <cuda_runtime.h>
#include <cuda_bf16.h>
#include <math.h>
#include <stdint.h>

#define BATCH 8
#define SEQL 2048
#define ROWS (BATCH*SEQL)     // 16384
#define DMODEL 256
#define DINNER 512
#define DSTATE 64
#define CONVDIM 640
#define DINPROJ 1153
#define NPADI 1280
#define NPROJ 1152            // gemm0 output cols (z + xBC)
#define ZSTRIDE 1280
#define QC 128
#define NCH (SEQL/QC)         // 16

// ---------------- scratch ----------------
__device__ float g_res[ROWS*DMODEL];
__device__ float g_hid[ROWS*DMODEL];
__device__ float g_zx [(size_t)ROWS*ZSTRIDE];
__device__ float g_xbc[ROWS*CONVDIM];
__device__ float g_y  [ROWS*DINNER];
__device__ float g_dt [ROWS];
__device__ float g_cum[ROWS];
__device__ float g_S[BATCH*NCH*DSTATE*DINNER];
__device__ float g_H[BATCH*NCH*DSTATE*DINNER];
__device__ float g_M[(size_t)BATCH*NCH*QC*QC];

// bf16 hi/lo operands
__device__ __nv_bfloat16 g_ah[ROWS*DMODEL], g_al[ROWS*DMODEL];
__device__ __nv_bfloat16 g_yh[ROWS*DINNER], g_yl[ROWS*DINNER];
__device__ __nv_bfloat16 g_wih[4*NPADI*DMODEL], g_wil[4*NPADI*DMODEL];
__device__ __nv_bfloat16 g_woh[4*DMODEL*DINNER], g_wol[4*DMODEL*DINNER];

__device__ __forceinline__ uint32_t smem_to_u32(const void* p) {
    uint32_t a;
    asm("{ .reg .u64 t; cvta.to.shared.u64 t, %1; cvt.u32.u64 %0, t; }" : "=r"(a) : "l"(p));
    return a;
}

// ---------------- one-shot weight conversion (fp32 -> bf16 hi/lo) ------------
__global__ __launch_bounds__(256) void k_wcvt(const float* __restrict__ ipw,
                                              const float* __restrict__ opw) {
    int idx = blockIdx.x*256 + threadIdx.x;
    const int NI = 4*NPADI*DMODEL;
    const int NO = 4*DMODEL*DINNER;
    if (idx < NI) {
        int l = idx / (NPADI*DMODEL);
        int r = (idx / DMODEL) % NPADI;
        int c = idx % DMODEL;
        float v = (r < DINPROJ) ? ipw[((size_t)l*DINPROJ + r)*DMODEL + c] : 0.f;
        __nv_bfloat16 h = __float2bfloat16(v);
        g_wih[idx] = h;
        g_wil[idx] = __float2bfloat16(v - __bfloat162float(h));
    } else if (idx - NI < NO) {
        int j = idx - NI;
        float v = opw[j];
        __nv_bfloat16 h = __float2bfloat16(v);
        g_woh[j] = h;
        g_wol[j] = __float2bfloat16(v - __bfloat162float(h));
    }
}

// ---------------- embed gather ----------------
__global__ __launch_bounds__(256) void k_embed(const int* __restrict__ ids,
                                               const float* __restrict__ embed) {
    int row = blockIdx.x, t = threadIdx.x;
    g_res[row*DMODEL + t] = embed[ids[row]*DMODEL + t];
}

// ---------------- residual add + rmsnorm -> bf16 hi/lo A --------------------
__global__ __launch_bounds__(256) void k_resnorm(const float* __restrict__ w, int add) {
    int row = blockIdx.x, t = threadIdx.x;
    float v = g_res[row*DMODEL + t];
    if (add) { v += g_hid[row*DMODEL + t]; g_res[row*DMODEL + t] = v; }
    float s = v*v;
    #pragma unroll
    for (int o = 16; o > 0; o >>= 1) s += __shfl_xor_sync(0xffffffffu, s, o);
    __shared__ float wred[8];
    if ((t & 31) == 0) wred[t >> 5] = s;
    __syncthreads();
    float tot = wred[0]+wred[1]+wred[2]+wred[3]+wred[4]+wred[5]+wred[6]+wred[7];
    float rs = rsqrtf(tot*(1.f/DMODEL) + 1e-5f);
    float o = v * rs * w[t];
    __nv_bfloat16 h = __float2bfloat16(o);
    g_ah[row*DMODEL + t] = h;
    g_al[row*DMODEL + t] = __float2bfloat16(o - __bfloat162float(h));
}

// ---------------- dt GEMV: dt_raw = (ah+al) . w_dt ---------------------------
__global__ __launch_bounds__(256) void k_dtproj(const float* __restrict__ wdt) {
    __shared__ float w[DMODEL];
    int tid = threadIdx.x;
    w[tid] = wdt[tid];
    __syncthreads();
    int wid = tid >> 5, lane = tid & 31;
    int row = blockIdx.x*8 + wid;
    size_t base = (size_t)row*DMODEL + lane*8;
    uint4 va = *(const uint4*)&g_ah[base];
    uint4 vl = *(const uint4*)&g_al[base];
    float s = 0.f;
    const uint32_t* pa = (const uint32_t*)&va;
    const uint32_t* pl = (const uint32_t*)&vl;
    #pragma unroll
    for (int j = 0; j < 4; j++) {
        __nv_bfloat162 a2 = *(const __nv_bfloat162*)&pa[j];
        __nv_bfloat162 l2 = *(const __nv_bfloat162*)&pl[j];
        float a0 = __bfloat162float(__low2bfloat16(a2)) + __bfloat162float(__low2bfloat16(l2));
        float a1 = __bfloat162float(__high2bfloat16(a2)) + __bfloat162float(__high2bfloat16(l2));
        s += a0*w[lane*8 + j*2] + a1*w[lane*8 + j*2 + 1];
    }
    #pragma unroll
    for (int o = 16; o > 0; o >>= 1) s += __shfl_xor_sync(0xffffffffu, s, o);
    if (lane == 0) g_zx[(size_t)row*ZSTRIDE + 1152] = s;
}

// =================== bf16 mma GEMM, cp.async pipelined ===================
#define KT 32
#define ASTRIDE 40
#define ARR_BYTES (128*ASTRIDE*2)        // 10240
#define STAGE_BYTES (4*ARR_BYTES)        // 40KB

#define LDM4(r, addr) \
    asm volatile("ldmatrix.sync.aligned.m8n8.x4.shared.b16 {%0,%1,%2,%3}, [%4];" \
        : "=r"((r)[0]), "=r"((r)[1]), "=r"((r)[2]), "=r"((r)[3]) : "r"(addr))

#define MMA16816(c, a, b0, b1) \
    asm volatile("mma.sync.aligned.m16n8k16.row.col.f32.bf16.bf16.f32 " \
        "{%0,%1,%2,%3}, {%4,%5,%6,%7}, {%8,%9}, {%0,%1,%2,%3};" \
        : "+f"((c)[0]), "+f"((c)[1]), "+f"((c)[2]), "+f"((c)[3]) \
        : "r"((a)[0]), "r"((a)[1]), "r"((a)[2]), "r"((a)[3]), "r"(b0), "r"(b1))

#define CPA16(s, g) \
    asm volatile("cp.async.cg.shared.global [%0], [%1], 16;" :: "r"(s), "l"(g))
#define CPA_COMMIT() asm volatile("cp.async.commit_group;" ::: "memory")
#define CPA_WAIT(n)  asm volatile("cp.async.wait_group %0;" :: "n"(n) : "memory")

__device__ __forceinline__ void gemm_load_stage(
    uint32_t base, const __nv_bfloat16* Ah, const __nv_bfloat16* Al,
    const __nv_bfloat16* Bh, const __nv_bfloat16* Bl,
    int m0, int n0, int k0, int K, int tid)
{
    #pragma unroll
    for (int j = 0; j < 8; j++) {
        int e = j*256 + tid;            // 0..2047
        int arr = e >> 9;
        int idx = e & 511;
        int row = idx >> 2, ch = idx & 3;
        const __nv_bfloat16* src;
        if (arr == 0)      src = Ah + (size_t)(m0+row)*K;
        else if (arr == 1) src = Al + (size_t)(m0+row)*K;
        else if (arr == 2) src = Bh + (size_t)(n0+row)*K;
        else               src = Bl + (size_t)(n0+row)*K;
        uint32_t saddr = base + (uint32_t)arr*ARR_BYTES + (uint32_t)(row*80 + ch*16);
        CPA16(saddr, src + k0 + ch*8);
    }
}

template<int NS>
__global__ __launch_bounds__(256, (NS==2)?2:1)
void gemm_bf3(int which, int woff, int K, int ldc) {
    extern __shared__ char smem[];
    const __nv_bfloat16 *Ah, *Al, *Bh, *Bl; float* C;
    if (which == 0) { Ah = g_ah; Al = g_al; Bh = g_wih + woff; Bl = g_wil + woff; C = g_zx; }
    else            { Ah = g_yh; Al = g_yl; Bh = g_woh + woff; Bl = g_wol + woff; C = g_hid; }

    uint32_t sb = smem_to_u32(smem);
    int tid = threadIdx.x;
    int wid = tid >> 5, lane = tid & 31;
    int m0 = blockIdx.y * 128;
    int n0 = blockIdx.x * 128;
    int wm = wid >> 2, wn = wid & 3;
    int nkt = K / KT;

    float c[4][4][4];
    #pragma unroll
    for (int i = 0; i < 4; i++)
        #pragma unroll
        for (int j = 0; j < 4; j++)
            #pragma unroll
            for (int q = 0; q < 4; q++) c[i][j][q] = 0.f;

    uint32_t a_off = (uint32_t)((lane & 15)*(ASTRIDE*2) + (lane >> 4)*16);
    uint32_t b_off = (uint32_t)(((lane & 7) + ((lane >> 4) << 3))*(ASTRIDE*2) + ((lane >> 3) & 1)*16);

    // prologue: stages 0..NS-2
    #pragma unroll
    for (int s = 0; s < NS-1; s++) {
        if (s < nkt) gemm_load_stage(sb + s*STAGE_BYTES, Ah, Al, Bh, Bl, m0, n0, s*KT, K, tid);
        CPA_COMMIT();
    }

    for (int kt = 0; kt < nkt; kt++) {
        CPA_WAIT(NS-2);
        __syncthreads();
        // issue next stage load AFTER the barrier: overlaps current mma, race-free
        int nx = kt + NS - 1;
        if (nx < nkt)
            gemm_load_stage(sb + (nx % NS)*STAGE_BYTES, Ah, Al, Bh, Bl, m0, n0, nx*KT, K, tid);
        CPA_COMMIT();

        uint32_t base = sb + (kt % NS)*STAGE_BYTES;
        uint32_t ahi = base, alo = base + ARR_BYTES;
        uint32_t bhi = base + 2*ARR_BYTES, blo = base + 3*ARR_BYTES;

        #pragma unroll
        for (int h = 0; h < 2; h++) {
            uint32_t kh = h*32;
            uint32_t Bhf[2][4], Blf[2][4];
            #pragma unroll
            for (int g = 0; g < 2; g++) {
                uint32_t rb = (uint32_t)((wn*32 + g*16)*(ASTRIDE*2)) + kh + b_off;
                LDM4(Bhf[g], bhi + rb);
                LDM4(Blf[g], blo + rb);
            }
            #pragma unroll
            for (int mf = 0; mf < 4; mf++) {
                uint32_t Ahf[4], Alf[4];
                uint32_t rb = (uint32_t)((wm*64 + mf*16)*(ASTRIDE*2)) + kh + a_off;
                LDM4(Ahf, ahi + rb);
                LDM4(Alf, alo + rb);
                #pragma unroll
                for (int nf = 0; nf < 4; nf++) {
                    int g = nf >> 1, o = (nf & 1)*2;
                    MMA16816(c[mf][nf], Ahf, Bhf[g][o], Bhf[g][o+1]);
                    MMA16816(c[mf][nf], Alf, Bhf[g][o], Bhf[g][o+1]);
                    MMA16816(c[mf][nf], Ahf, Blf[g][o], Blf[g][o+1]);
                }
            }
        }
    }

    #pragma unroll
    for (int mf = 0; mf < 4; mf++) {
        int r0 = m0 + wm*64 + mf*16 + (lane >> 2);
        #pragma unroll
        for (int nf = 0; nf < 4; nf++) {
            int col = n0 + wn*32 + nf*8 + (lane & 3)*2;
            *(float2*)&C[(size_t)r0*ldc + col]     = make_float2(c[mf][nf][0], c[mf][nf][1]);
            *(float2*)&C[(size_t)(r0+8)*ldc + col] = make_float2(c[mf][nf][2], c[mf][nf][3]);
        }
    }
}

// ---------------- conv: 4 channels x 4 timesteps per thread ------------------
__global__ __launch_bounds__(256) void k_conv(const float* __restrict__ cw,
                                              const float* __restrict__ cb) {
    int idx = blockIdx.x*256 + threadIdx.x;
    if (idx >= (ROWS/4)*(CONVDIM/4)) return;
    int c  = (idx % (CONVDIM/4))*4;
    int tg = idx / (CONVDIM/4);
    int row0 = tg*4;
    int t0 = row0 & (SEQL-1);
    float4 q0 = *(const float4*)&cw[(c+0)*4];
    float4 q1 = *(const float4*)&cw[(c+1)*4];
    float4 q2 = *(const float4*)&cw[(c+2)*4];
    float4 q3 = *(const float4*)&cw[(c+3)*4];
    float4 bias = *(const float4*)&cb[c];
    const float* base = g_zx + (size_t)row0*ZSTRIDE + DINNER + c;
    float4 v[7];
    #pragma unroll
    for (int j = 0; j < 3; j++)
        v[j] = (t0 + j >= 3) ? *(const float4*)&base[(j-3)*ZSTRIDE]
                             : make_float4(0.f,0.f,0.f,0.f);
    #pragma unroll
    for (int j = 3; j < 7; j++)
        v[j] = *(const float4*)&base[(j-3)*ZSTRIDE];
    #pragma unroll
    for (int k = 0; k < 4; k++) {
        float a0 = bias.x + v[k].x*q0.x + v[k+1].x*q0.y + v[k+2].x*q0.z + v[k+3].x*q0.w;
        float a1 = bias.y + v[k].y*q1.x + v[k+1].y*q1.y + v[k+2].y*q1.z + v[k+3].y*q1.w;
        float a2 = bias.z + v[k].z*q2.x + v[k+1].z*q2.y + v[k+2].z*q2.z + v[k+3].z*q2.w;
        float a3 = bias.w + v[k].w*q3.x + v[k+1].w*q3.y + v[k+2].w*q3.z + v[k+3].w*q3.w;
        float4 o;
        o.x = a0 / (1.f + expf(-a0));
        o.y = a1 / (1.f + expf(-a1));
        o.z = a2 / (1.f + expf(-a2));
        o.w = a3 / (1.f + expf(-a3));
        *(float4*)&g_xbc[(size_t)(row0+k)*CONVDIM + c] = o;
    }
}

// ---------------- k_M: dt softplus + cumsum + chunk M matrix (transposed) ----
#define MPAD 65
#define KM_SMEM ((2*QC*MPAD + 2*QC)*4)
__global__ __launch_bounds__(256) void k_M(const float* __restrict__ dtb,
                                           const float* __restrict__ alog,
                                           const float* __restrict__ dparam) {
    extern __shared__ float sm[];
    float* Bs   = sm;
    float* Cs   = Bs + QC*MPAD;
    float* scum = Cs + QC*MPAD;
    float* sdt  = scum + QC;
    int bc = blockIdx.x;
    int tid = threadIdx.x;
    int rowbase = (bc >> 4)*SEQL + (bc & 15)*QC;

    if (tid < QC) {
        float raw = g_zx[(size_t)(rowbase+tid)*ZSTRIDE + 1152] + dtb[0];
        sdt[tid] = (raw > 20.f) ? raw : log1pf(expf(raw));
    }
    #pragma unroll
    for (int j = 0; j < 32; j++) {
        int e = j*256 + tid; int ii = e >> 6, n = e & 63;
        const float* src = g_xbc + (size_t)(rowbase+ii)*CONVDIM + DINNER;
        Bs[ii*MPAD + n] = src[n];
        Cs[ii*MPAD + n] = src[DSTATE + n];
    }
    __syncthreads();
    if (tid == 0) {
        float A = -expf(alog[0]);
        float cacc = 0.f;
        for (int j = 0; j < QC; j++) { cacc += sdt[j]*A; scum[j] = cacc; }
    }
    __syncthreads();
    if (tid < QC) { g_dt[rowbase+tid] = sdt[tid]; g_cum[rowbase+tid] = scum[tid]; }

    int i  = tid >> 1;
    int s0 = (tid & 1)*64;
    float dpv = dparam[0];
    float ci  = scum[i];
    float* Mo = g_M + ((size_t)bc*QC)*QC;
    for (int sj = 0; sj < 64; sj++) {
        int s = s0 + sj;
        float m = 0.f;
        if (s <= i) {
            float dot = 0.f;
            #pragma unroll 16
            for (int n = 0; n < 64; n++) dot += Cs[i*MPAD+n]*Bs[s*MPAD+n];
            m = expf(ci - scum[s]) * sdt[s] * dot;
            if (s == i) m += dpv;
        }
        Mo[(size_t)s*QC + i] = m;
    }
}

// ---------------- chunk state S ----------------
__global__ __launch_bounds__(256) void k_S() {
    int bc = blockIdx.x;
    int pt = blockIdx.y;
    int rowbase = (bc >> 4)*SEQL + (bc & 15)*QC;
    float cl = g_cum[rowbase + QC - 1];
    __shared__ __align__(16) float Bw[16][64];
    __shared__ __align__(16) float Xs[16][128];
    int tid = threadIdx.x;
    int nt = tid >> 4, ptg = tid & 15;
    float acc[4][8];
    #pragma unroll
    for (int a = 0; a < 4; a++)
        #pragma unroll
        for (int b = 0; b < 8; b++) acc[a][b] = 0.f;

    int eb = tid*4; int bii = eb >> 6, bn0 = eb & 63;
    int ex = tid*8; int xii = ex >> 7, xp0 = ex & 127;

    for (int i0 = 0; i0 < QC; i0 += 16) {
        int rb = rowbase + i0 + bii;
        float coef = expf(cl - g_cum[rb]) * g_dt[rb];
        #pragma unroll
        for (int j = 0; j < 4; j++)
            Bw[bii][bn0+j] = coef * g_xbc[(size_t)rb*CONVDIM + DINNER + bn0 + j];
        int rx = rowbase + i0 + xii;
        #pragma unroll
        for (int j = 0; j < 8; j++)
            Xs[xii][xp0+j] = g_xbc[(size_t)rx*CONVDIM + pt*128 + xp0 + j];
        __syncthreads();
        #pragma unroll
        for (int kk = 0; kk < 16; kk++) {
            float4 av = *(const float4*)&Bw[kk][nt*4];
            float a[4] = {av.x, av.y, av.z, av.w};
            #pragma unroll
            for (int q = 0; q < 2; q++) {
                float4 xv = *(const float4*)&Xs[kk][ptg*4 + q*64];
                #pragma unroll
                for (int nn = 0; nn < 4; nn++) {
                    acc[nn][q*4+0] += a[nn]*xv.x;
                    acc[nn][q*4+1] += a[nn]*xv.y;
                    acc[nn][q*4+2] += a[nn]*xv.z;
                    acc[nn][q*4+3] += a[nn]*xv.w;
                }
            }
        }
        __syncthreads();
    }
    #pragma unroll
    for (int nn = 0; nn < 4; nn++) {
        int n = nt*4 + nn;
        #pragma unroll
        for (int q = 0; q < 2; q++) {
            float4 st = make_float4(acc[nn][q*4], acc[nn][q*4+1], acc[nn][q*4+2], acc[nn][q*4+3]);
            *(float4*)&g_S[((size_t)bc*DSTATE + n)*DINNER + pt*128 + ptg*4 + q*64] = st;
        }
    }
}

// ---------------- chunk-boundary recurrence ----------------
__global__ __launch_bounds__(256) void k_H() {
    int b = blockIdx.x, ps = blockIdx.y;
    int tid = threadIdx.x;
    int n = tid >> 2;
    int p0 = ps*64 + (tid & 3)*16;
    float h[16];
    #pragma unroll
    for (int q = 0; q < 16; q++) h[q] = 0.f;
    for (int c = 0; c < NCH; c++) {
        size_t base = ((size_t)(b*NCH + c)*DSTATE + n)*DINNER + p0;
        #pragma unroll
        for (int q = 0; q < 4; q++)
            *(float4*)&g_H[base + q*4] = make_float4(h[q*4], h[q*4+1], h[q*4+2], h[q*4+3]);
        float dec = expf(g_cum[b*SEQL + c*QC + QC - 1]);
        #pragma unroll
        for (int q = 0; q < 4; q++) {
            float4 s4 = *(const float4*)&g_S[base + q*4];
            h[q*4+0] = h[q*4+0]*dec + s4.x;
            h[q*4+1] = h[q*4+1]*dec + s4.y;
            h[q*4+2] = h[q*4+2]*dec + s4.z;
            h[q*4+3] = h[q*4+3]*dec + s4.w;
        }
    }
}

// ---------------- k_Yc: y_raw = M.X + E*(C.H0) per (chunk, p-quarter) --------
#define CTPAD 132
#define KYC_SMEM ((QC*QC + QC*128 + DSTATE*CTPAD + DSTATE*128)*4)
__global__ __launch_bounds__(256, 1) void k_Yc() {
    extern __shared__ float sm[];
    float* Mt = sm;
    float* Xs = Mt + QC*QC;
    float* Ct = Xs + QC*128;
    float* Hs = Ct + DSTATE*CTPAD;
    int bc = blockIdx.x;
    int pq = blockIdx.y;
    int tid = threadIdx.x;
    int rowbase = (bc >> 4)*SEQL + (bc & 15)*QC;
    int p0 = pq*128;

    const float4* Msrc = (const float4*)(g_M + (size_t)bc*QC*QC);
    #pragma unroll
    for (int j = 0; j < 16; j++) {
        int e = j*256 + tid;
        ((float4*)Mt)[e] = Msrc[e];
    }
    #pragma unroll
    for (int j = 0; j < 16; j++) {
        int e = j*256 + tid; int s = e >> 5, p4 = e & 31;
        ((float4*)Xs)[e] = *(const float4*)&g_xbc[(size_t)(rowbase+s)*CONVDIM + p0 + p4*4];
    }
    #pragma unroll
    for (int j = 0; j < 8; j++) {
        int e = j*256 + tid; int n = e >> 5, p4 = e & 31;
        *(float4*)&Hs[n*128 + p4*4] = *(const float4*)&g_H[((size_t)bc*DSTATE + n)*DINNER + p0 + p4*4];
    }
    #pragma unroll
    for (int j = 0; j < 32; j++) {
        int e = j*256 + tid; int ii = e >> 6, n = e & 63;
        Ct[n*CTPAD + ii] = g_xbc[(size_t)(rowbase+ii)*CONVDIM + DINNER + DSTATE + n];
    }
    __syncthreads();

    int w = tid >> 5, lane = tid & 31;
    int r0 = w*16 + (lane >> 4)*8;
    int c0 = (lane & 15)*8;
    float acc[8][8];
    #pragma unroll
    for (int r = 0; r < 8; r++)
        #pragma unroll
        for (int cc = 0; cc < 8; cc++) acc[r][cc] = 0.f;

    int kmax = w*16 + 16;
    for (int k = 0; k < kmax; k++) {
        float4 m0 = *(const float4*)&Mt[k*128 + r0];
        float4 m1 = *(const float4*)&Mt[k*128 + r0 + 4];
        float4 x0 = *(const float4*)&Xs[k*128 + c0];
        float4 x1 = *(const float4*)&Xs[k*128 + c0 + 4];
        float mm[8] = {m0.x,m0.y,m0.z,m0.w,m1.x,m1.y,m1.z,m1.w};
        float xx[8] = {x0.x,x0.y,x0.z,x0.w,x1.x,x1.y,x1.z,x1.w};
        #pragma unroll
        for (int r = 0; r < 8; r++)
            #pragma unroll
            for (int cc = 0; cc < 8; cc++) acc[r][cc] += mm[r]*xx[cc];
    }

    if (bc & 15) {
        float Er[8];
        #pragma unroll
        for (int r = 0; r < 8; r++) Er[r] = expf(g_cum[rowbase + r0 + r]);
        for (int n = 0; n < DSTATE; n++) {
            float4 cv0 = *(const float4*)&Ct[n*CTPAD + r0];
            float4 cv1 = *(const float4*)&Ct[n*CTPAD + r0 + 4];
            float4 h0 = *(const float4*)&Hs[n*128 + c0];
            float4 h1 = *(const float4*)&Hs[n*128 + c0 + 4];
            float mm[8] = {cv0.x*Er[0],cv0.y*Er[1],cv0.z*Er[2],cv0.w*Er[3],
                           cv1.x*Er[4],cv1.y*Er[5],cv1.z*Er[6],cv1.w*Er[7]};
            float hh[8] = {h0.x,h0.y,h0.z,h0.w,h1.x,h1.y,h1.z,h1.w};
            #pragma unroll
            for (int r = 0; r < 8; r++)
                #pragma unroll
                for (int cc = 0; cc < 8; cc++) acc[r][cc] += mm[r]*hh[cc];
        }
    }

    #pragma unroll
    for (int r = 0; r < 8; r++) {
        float* dst = g_y + (size_t)(rowbase + r0 + r)*DINNER + p0 + c0;
        *(float4*)dst       = make_float4(acc[r][0], acc[r][1], acc[r][2], acc[r][3]);
        *(float4*)(dst + 4) = make_float4(acc[r][4], acc[r][5], acc[r][6], acc[r][7]);
    }
}

// ---------------- k_gate: yh/yl = hi/lo(rmsnorm(y_raw * silu(z)) * ngw) ------
__global__ __launch_bounds__(128) void k_gate(const float* __restrict__ ngw) {
    int row = blockIdx.x, tid = threadIdx.x;
    float4 y = *(const float4*)&g_y[(size_t)row*DINNER + tid*4];
    float4 z = *(const float4*)&g_zx[(size_t)row*ZSTRIDE + tid*4];
    float g0 = y.x * (z.x / (1.f + expf(-z.x)));
    float g1 = y.y * (z.y / (1.f + expf(-z.y)));
    float g2 = y.z * (z.z / (1.f + expf(-z.z)));
    float g3 = y.w * (z.w / (1.f + expf(-z.w)));
    float s = g0*g0 + g1*g1 + g2*g2 + g3*g3;
    #pragma unroll
    for (int o = 16; o > 0; o >>= 1) s += __shfl_xor_sync(0xffffffffu, s, o);
    __shared__ float wred[4];
    if ((tid & 31) == 0) wred[tid >> 5] = s;
    __syncthreads();
    float tot = wred[0] + wred[1] + wred[2] + wred[3];
    float rs = rsqrtf(tot*(1.f/DINNER) + 1e-5f);
    float4 gw = *(const float4*)&ngw[tid*4];
    float o0 = g0*rs*gw.x, o1 = g1*rs*gw.y, o2 = g2*rs*gw.z, o3 = g3*rs*gw.w;
    size_t base = (size_t)row*DINNER + tid*4;
    __nv_bfloat162 hp01 = __floats2bfloat162_rn(o0, o1);
    __nv_bfloat162 hp23 = __floats2bfloat162_rn(o2, o3);
    *(uint2*)&g_yh[base] = make_uint2(*(uint32_t*)&hp01, *(uint32_t*)&hp23);
    float r0 = o0 - __bfloat162float(__low2bfloat16(hp01));
    float r1 = o1 - __bfloat162float(__high2bfloat16(hp01));
    float r2 = o2 - __bfloat162float(__low2bfloat16(hp23));
    float r3 = o3 - __bfloat162float(__high2bfloat16(hp23));
    __nv_bfloat162 lp01 = __floats2bfloat162_rn(r0, r1);
    __nv_bfloat162 lp23 = __floats2bfloat162_rn(r2, r3);
    *(uint2*)&g_yl[base] = make_uint2(*(uint32_t*)&lp01, *(uint32_t*)&lp23);
}

// ---------------- final ----------------
__global__ __launch_bounds__(256) void k_final(const float* __restrict__ nfw,
                                               const float* __restrict__ embed,
                                               float* __restrict__ out) {
    int b = blockIdx.x, t = threadIdx.x;
    int row = b*SEQL + SEQL - 1;
    float v = g_res[row*DMODEL + t] + g_hid[row*DMODEL + t];
    __shared__ float fin[256];
    __shared__ float sred[256];
    sred[t] = v*v; __syncthreads();
    #pragma unroll
    for (int s = 128; s > 0; s >>= 1) {
        if (t < s) sred[t] += sred[t+s];
        __syncthreads();
    }
    float rs = rsqrtf(sred[0]*(1.f/DMODEL) + 1e-5f);
    fin[t] = v*rs*nfw[t]; __syncthreads();
    if (t < 100) {
        float accv = 0.f;
        #pragma unroll 8
        for (int d = 0; d < DMODEL; d++) accv += fin[d]*embed[t*DMODEL + d];
        out[b*100 + t] = accv;
    }
}

// ---------------- launch ----------------
extern "C" void kernel_launch(void* const* d_in, const int* in_sizes, int n_in,
                              void* d_out, int out_size) {
    const int*   ids   = (const int*)  d_in[0];
    const float* embed = (const float*)d_in[1];
    const float* ipw   = (const float*)d_in[2];
    const float* cw    = (const float*)d_in[3];
    const float* cb    = (const float*)d_in[4];
    const float* dtb   = (const float*)d_in[5];
    const float* alog  = (const float*)d_in[6];
    const float* dpar  = (const float*)d_in[7];
    const float* ngw   = (const float*)d_in[8];
    const float* opw   = (const float*)d_in[9];
    const float* bnw   = (const float*)d_in[10];
    const float* nfw   = (const float*)d_in[11];
    float* out = (float*)d_out;

    cudaFuncSetAttribute(gemm_bf3<2>, cudaFuncAttributeMaxDynamicSharedMemorySize, 2*STAGE_BYTES);
    cudaFuncSetAttribute(k_M,  cudaFuncAttributeMaxDynamicSharedMemorySize, KM_SMEM);
    cudaFuncSetAttribute(k_Yc, cudaFuncAttributeMaxDynamicSharedMemorySize, KYC_SMEM);

    int wtot = 4*NPADI*DMODEL + 4*DMODEL*DINNER;
    k_wcvt<<<(wtot + 255)/256, 256>>>(ipw, opw);
    k_embed<<<ROWS, 256>>>(ids, embed);
    for (int L = 0; L < 4; L++) {
        k_resnorm<<<ROWS, 256>>>(bnw + L*DMODEL, L > 0);
        gemm_bf3<2><<<dim3(NPROJ/128, ROWS/128), 256, 2*STAGE_BYTES>>>(0, L*NPADI*DMODEL,
                                                                       DMODEL, ZSTRIDE);
        k_dtproj<<<ROWS/8, 256>>>(ipw + ((size_t)L*DINPROJ + 1152)*DMODEL);
        k_conv<<<((ROWS/4)*(CONVDIM/4) + 255)/256, 256>>>(cw + L*CONVDIM*4, cb + L*CONVDIM);
        k_M<<<BATCH*NCH, 256, KM_SMEM>>>(dtb + L, alog + L, dpar + L);
        k_S<<<dim3(BATCH*NCH, 4), 256>>>();
        k_H<<<dim3(BATCH, 8), 256>>>();
        k_Yc<<<dim3(BATCH*NCH, 4), 256, KYC_SMEM>>>();
        k_gate<<<ROWS, 128>>>(ngw + L*DINNER);
        gemm_bf3<2><<<dim3(2, ROWS/128), 256, 2*STAGE_BYTES>>>(1, L*DMODEL*DINNER,
                                                               DINNER, DMODEL);
    }
    k_final<<<BATCH, 256>>>(nfw, embed, out);
}